// round 5
// baseline (speedup 1.0000x reference)
#include <cuda_runtime.h>
#include <cuda_bf16.h>
#include <cstdint>

// ---------------- problem constants ----------------
#define HD   64
#define NHEADS 4
#define NMAX 50000
#define FMAX 256

// ---------------- device scratch ----------------
__device__ float g_h[(size_t)NMAX * FMAX];     // gemm output
__device__ float g_acc[(size_t)NMAX * FMAX];   // scatter accumulator / L2 bn out
__device__ float g_res[(size_t)NMAX * FMAX];   // residual
__device__ __nv_bfloat16 g_ah[(size_t)NMAX * FMAX];
__device__ __nv_bfloat16 g_al[(size_t)NMAX * FMAX];
__device__ __nv_bfloat16 g_wh[FMAX * FMAX];
__device__ __nv_bfloat16 g_wl[FMAX * FMAX];
__device__ float g_als[NMAX * NHEADS];
__device__ float g_ald[NMAX * NHEADS];
__device__ float g_den[NMAX * NHEADS];
__device__ float g_sums[FMAX];
__device__ float g_sumsq[FMAX];

// ---------------- PTX helpers ----------------
__device__ __forceinline__ uint32_t smem_u32(const void* p) {
    uint32_t a;
    asm("{ .reg .u64 t; cvta.to.shared.u64 t, %1; cvt.u32.u64 %0, t; }" : "=r"(a) : "l"(p));
    return a;
}
__device__ __forceinline__ void redAdd4(float* addr, float a, float b, float c, float d) {
    asm volatile("red.global.add.v4.f32 [%0], {%1,%2,%3,%4};"
                 :: "l"(addr), "f"(a), "f"(b), "f"(c), "f"(d) : "memory");
}
#define LDMATRIX_X4(R0, R1, R2, R3, ADDR)                                   \
    asm volatile("ldmatrix.sync.aligned.m8n8.x4.shared.b16 {%0,%1,%2,%3}, [%4];" \
                 : "=r"(R0), "=r"(R1), "=r"(R2), "=r"(R3) : "r"(ADDR))
#define MMA_BF16(C, A, B)                                                   \
    asm volatile("mma.sync.aligned.m16n8k16.row.col.f32.bf16.bf16.f32 "     \
                 "{%0,%1,%2,%3}, {%4,%5,%6,%7}, {%8,%9}, {%0,%1,%2,%3};"    \
                 : "+f"((C)[0]), "+f"((C)[1]), "+f"((C)[2]), "+f"((C)[3])   \
                 : "r"((A)[0]), "r"((A)[1]), "r"((A)[2]), "r"((A)[3]),      \
                   "r"((B)[0]), "r"((B)[1]))

// ---------------- fp32 -> bf16 hi/lo split ----------------
__global__ void split_bf16_kernel(const float4* __restrict__ in,
                                  __nv_bfloat162* __restrict__ hi,
                                  __nv_bfloat162* __restrict__ lo, int n4) {
    int i = blockIdx.x * blockDim.x + threadIdx.x;
    if (i >= n4) return;
    float4 v = in[i];
    __nv_bfloat16 h0 = __float2bfloat16(v.x), h1 = __float2bfloat16(v.y);
    __nv_bfloat16 h2 = __float2bfloat16(v.z), h3 = __float2bfloat16(v.w);
    float r0 = v.x - __bfloat162float(h0), r1 = v.y - __bfloat162float(h1);
    float r2 = v.z - __bfloat162float(h2), r3 = v.w - __bfloat162float(h3);
    hi[i * 2 + 0] = __nv_bfloat162(h0, h1);
    hi[i * 2 + 1] = __nv_bfloat162(h2, h3);
    lo[i * 2 + 0] = __nv_bfloat162(__float2bfloat16(r0), __float2bfloat16(r1));
    lo[i * 2 + 1] = __nv_bfloat162(__float2bfloat16(r2), __float2bfloat16(r3));
}

// ---------------- HMMA GEMM: C[n,m] = sum_k A[n,k]*W[m,k], 3-split bf16 ----------------
// A(hi/lo) [Nrows,K] bf16 K-major, W(hi/lo) [NOUT,K] bf16 K-major.
// CTA tile: 128 rows x NTILE cols. 256 threads (8 warps).
template<int NTILE>
__global__ void __launch_bounds__(256) gemm_mma(
    const __nv_bfloat16* __restrict__ Ah, const __nv_bfloat16* __restrict__ Al,
    const __nv_bfloat16* __restrict__ Wh, const __nv_bfloat16* __restrict__ Wl,
    float* __restrict__ C, int Nrows, int K, int NOUT) {
    constexpr int RS = 40;                        // smem row stride (bf16) -> 80B, conflict-free
    constexpr int MT = (NTILE == 128) ? 2 : 1;    // m16 tiles per warp
    constexpr int WN = NTILE / 64;                // warps along n
    __shared__ __nv_bfloat16 As[128 * RS];
    __shared__ __nv_bfloat16 Ws[NTILE * RS];
    const int tid = threadIdx.x, lane = tid & 31, wid = tid >> 5;
    const int wm = wid / WN, wn = wid % WN;
    const int row0 = blockIdx.x * 128, col0 = blockIdx.y * NTILE;
    const uint32_t asb = smem_u32(As), wsb = smem_u32(Ws);

    // ldmatrix lane address pieces (non-transposed 8x8 b16 tiles)
    const int a_row  = ((lane >> 3) & 1) * 8 + (lane & 7);
    const int a_koff = ((lane >> 4) & 1) * 8;
    const int b_row  = ((lane >> 4) & 1) * 8 + (lane & 7);
    const int b_koff = ((lane >> 3) & 1) * 8;
    const uint32_t a_base = asb + (uint32_t)(((wm * 16 * MT + a_row) * RS + a_koff) * 2);
    const uint32_t b_base = wsb + (uint32_t)(((wn * 64 + b_row) * RS + b_koff) * 2);

    float acc[MT][8][4];
    #pragma unroll
    for (int mt = 0; mt < MT; mt++)
        #pragma unroll
        for (int nt = 0; nt < 8; nt++)
            #pragma unroll
            for (int j = 0; j < 4; j++) acc[mt][nt][j] = 0.f;

    #pragma unroll 1
    for (int ph = 0; ph < 3; ph++) {
        const __nv_bfloat16* Ap = (ph == 1) ? Al : Ah;
        const __nv_bfloat16* Wp = (ph == 2) ? Wl : Wh;
        #pragma unroll 1
        for (int k0 = 0; k0 < K; k0 += 32) {
            for (int i = tid; i < 512; i += 256) {
                int r = i >> 2, cv = (i & 3) * 8;
                int gr = row0 + r;
                uint4 v = make_uint4(0u, 0u, 0u, 0u);
                if (gr < Nrows) v = *(const uint4*)(Ap + (size_t)gr * K + k0 + cv);
                *(uint4*)&As[r * RS + cv] = v;
            }
            for (int i = tid; i < NTILE * 4; i += 256) {
                int r = i >> 2, cv = (i & 3) * 8;
                uint4 v = *(const uint4*)(Wp + (size_t)(col0 + r) * K + k0 + cv);
                *(uint4*)&Ws[r * RS + cv] = v;
            }
            __syncthreads();
            #pragma unroll
            for (int kk = 0; kk < 32; kk += 16) {
                uint32_t a[MT][4];
                #pragma unroll
                for (int mt = 0; mt < MT; mt++) {
                    uint32_t addr = a_base + (uint32_t)((mt * 16 * RS + kk) * 2);
                    LDMATRIX_X4(a[mt][0], a[mt][1], a[mt][2], a[mt][3], addr);
                }
                uint32_t b[8][2];
                #pragma unroll
                for (int nt16 = 0; nt16 < 4; nt16++) {
                    uint32_t r0, r1, r2, r3;
                    uint32_t addr = b_base + (uint32_t)((nt16 * 16 * RS + kk) * 2);
                    LDMATRIX_X4(r0, r1, r2, r3, addr);
                    b[nt16 * 2 + 0][0] = r0; b[nt16 * 2 + 0][1] = r1;
                    b[nt16 * 2 + 1][0] = r2; b[nt16 * 2 + 1][1] = r3;
                }
                #pragma unroll
                for (int mt = 0; mt < MT; mt++)
                    #pragma unroll
                    for (int nt = 0; nt < 8; nt++)
                        MMA_BF16(acc[mt][nt], a[mt], b[nt]);
            }
            __syncthreads();
        }
    }
    #pragma unroll
    for (int mt = 0; mt < MT; mt++) {
        int mrow = row0 + wm * 16 * MT + mt * 16 + (lane >> 2);
        #pragma unroll
        for (int nt = 0; nt < 8; nt++) {
            int ncol = col0 + wn * 64 + nt * 8 + (lane & 3) * 2;
            if (mrow < Nrows)
                *(float2*)&C[(size_t)mrow * NOUT + ncol] = make_float2(acc[mt][nt][0], acc[mt][nt][1]);
            if (mrow + 8 < Nrows)
                *(float2*)&C[(size_t)(mrow + 8) * NOUT + ncol] = make_float2(acc[mt][nt][2], acc[mt][nt][3]);
        }
    }
}

// ---------------- attention logits ----------------
__global__ void logits_kernel(const float* __restrict__ h,
                              const float* __restrict__ a_s, const float* __restrict__ a_d,
                              float* __restrict__ als, float* __restrict__ ald,
                              int N, int Hh) {
    int idx = blockIdx.x * blockDim.x + threadIdx.x;
    if (idx >= N * Hh) return;
    int n = idx / Hh, hh = idx - n * Hh;
    const float4* hp = (const float4*)(h + (size_t)n * Hh * HD + hh * HD);
    const float4* ps = (const float4*)(a_s + hh * HD);
    const float4* pd = (const float4*)(a_d + hh * HD);
    float ss = 0.f, sd = 0.f;
    #pragma unroll
    for (int c = 0; c < HD / 4; c++) {
        float4 v = hp[c], s4 = ps[c], d4 = pd[c];
        ss += v.x * s4.x + v.y * s4.y + v.z * s4.z + v.w * s4.w;
        sd += v.x * d4.x + v.y * d4.y + v.z * d4.z + v.w * d4.w;
    }
    als[idx] = ss;
    ald[idx] = sd;
}

// ---------------- zero fill ----------------
__global__ void zero4_kernel(float4* __restrict__ p, int n4) {
    int i = blockIdx.x * blockDim.x + threadIdx.x;
    if (i < n4) p[i] = make_float4(0.f, 0.f, 0.f, 0.f);
}
__global__ void zero_stats_kernel(float* __restrict__ s, float* __restrict__ s2) {
    s[threadIdx.x] = 0.f;
    s2[threadIdx.x] = 0.f;
}

// ---------------- fused edge pass: den += ex; acc[dst] += ex*h[src] ----------------
__device__ __forceinline__ void edge_sd(const int* __restrict__ ei, int e, int E,
                                        int& s, int& d) {
    if (e < E) { s = ei[e]; d = ei[E + e]; }
    else       { s = d = e - E; }
}

__global__ void scatter_fused_kernel(const int* __restrict__ ei, int E, int N, int Hh,
                                     const float* __restrict__ als, const float* __restrict__ ald,
                                     const float* __restrict__ h,
                                     float* __restrict__ den, float* __restrict__ acc) {
    int gw = (blockIdx.x * blockDim.x + threadIdx.x) >> 5;
    int lane = threadIdx.x & 31;
    int EE = E + N;
    if (gw >= EE) return;
    int s, d;
    edge_sd(ei, gw, E, s, d);
    float ev = 0.f;
    if (lane < Hh) {
        float v = als[s * Hh + lane] + ald[d * Hh + lane];
        v = v > 0.f ? v : 0.2f * v;
        ev = __expf(v);
        atomicAdd(&den[d * Hh + lane], ev);
    }
    int F = Hh * HD;
    const float4* hs = (const float4*)(h + (size_t)s * F);
    float* od = acc + (size_t)d * F;
    for (int c4 = lane; c4 < F / 4; c4 += 32) {
        float al = __shfl_sync(0xffffffff, ev, c4 >> 4);  // head = c4/(HD/4)
        float4 v = hs[c4];
        redAdd4(od + c4 * 4, v.x * al, v.y * al, v.z * al, v.w * al);
    }
}

// ---------------- finalize (+BN stats) ----------------
// out[n,f] = acc[n,f]/den[n, f>>6] + bias[f]; accumulate per-feature sums
__global__ void finalize_stats_kernel(const float* __restrict__ acc, const float* __restrict__ den,
                                      const float* __restrict__ bias, float* __restrict__ out,
                                      int N, float* __restrict__ sums, float* __restrict__ sumsq) {
    int f = threadIdx.x;  // 256
    float bf = bias[f];
    int rows_per = (N + gridDim.x - 1) / gridDim.x;
    int r0 = blockIdx.x * rows_per;
    int r1 = min(N, r0 + rows_per);
    float s = 0.f, s2 = 0.f;
    for (int r = r0; r < r1; r++) {
        float v = acc[(size_t)r * FMAX + f] / den[r * NHEADS + (f >> 6)] + bf;
        out[(size_t)r * FMAX + f] = v;
        s += v;
        s2 += v * v;
    }
    atomicAdd(&sums[f], s);
    atomicAdd(&sumsq[f], s2);
}

// layer-3 finalize in place: out = out/den + bias (H=1, F=64)
__global__ void finalize_out_kernel(float* __restrict__ out, const float* __restrict__ den,
                                    const float* __restrict__ bias, int N) {
    int idx = blockIdx.x * blockDim.x + threadIdx.x;
    if (idx >= N * HD) return;
    int n = idx >> 6, f = idx & 63;
    out[idx] = out[idx] / den[n] + bias[f];
}

// ---------------- batch norm apply ----------------
__global__ void bn_apply_kernel(const float* __restrict__ x, const float* __restrict__ res,
                                const float* __restrict__ gamma, const float* __restrict__ beta,
                                const float* __restrict__ sums, const float* __restrict__ sumsq,
                                int N, float* __restrict__ out) {
    int idx = blockIdx.x * blockDim.x + threadIdx.x;
    if (idx >= N * FMAX) return;
    int f = idx & (FMAX - 1);
    float inv_n = 1.0f / (float)N;
    float mu = sums[f] * inv_n;
    float var = sumsq[f] * inv_n - mu * mu;
    float v = gamma[f] * (x[idx] - mu) * rsqrtf(var + 1e-5f) + beta[f];
    v = v > 0.f ? v : 0.01f * v;
    if (res) v += res[idx];
    out[idx] = v;
}

// ---------------- host orchestration ----------------
static void run_split(const float* in, __nv_bfloat16* hi, __nv_bfloat16* lo, int n) {
    int n4 = n / 4;
    split_bf16_kernel<<<(n4 + 255) / 256, 256>>>((const float4*)in,
                                                 (__nv_bfloat162*)hi, (__nv_bfloat162*)lo, n4);
}
static void run_zero(float* p, size_t n) {
    int n4 = (int)(n / 4);
    zero4_kernel<<<(n4 + 255) / 256, 256>>>((float4*)p, n4);
}

extern "C" void kernel_launch(void* const* d_in, const int* in_sizes, int n_in,
                              void* d_out, int out_size) {
    const float* x     = (const float*)d_in[0];
    const int*   ei    = (const int*)d_in[1];
    const float* W1    = (const float*)d_in[2];
    const float* a1s   = (const float*)d_in[3];
    const float* a1d   = (const float*)d_in[4];
    const float* b1    = (const float*)d_in[5];
    const float* W2    = (const float*)d_in[6];
    const float* a2s   = (const float*)d_in[7];
    const float* a2d   = (const float*)d_in[8];
    const float* b2    = (const float*)d_in[9];
    const float* W3    = (const float*)d_in[10];
    const float* a3s   = (const float*)d_in[11];
    const float* a3d   = (const float*)d_in[12];
    const float* b3    = (const float*)d_in[13];
    const float* gamma = (const float*)d_in[14];
    const float* beta  = (const float*)d_in[15];
    float* out = (float*)d_out;

    int N = in_sizes[0] / (2 * HD);
    int E = in_sizes[1] / 2;
    int EE = E + N;

    float *h, *acc, *res, *als, *ald, *den, *sums, *sumsq;
    __nv_bfloat16 *ah, *al, *wh, *wl;
    cudaGetSymbolAddress((void**)&h,     g_h);
    cudaGetSymbolAddress((void**)&acc,   g_acc);
    cudaGetSymbolAddress((void**)&res,   g_res);
    cudaGetSymbolAddress((void**)&ah,    g_ah);
    cudaGetSymbolAddress((void**)&al,    g_al);
    cudaGetSymbolAddress((void**)&wh,    g_wh);
    cudaGetSymbolAddress((void**)&wl,    g_wl);
    cudaGetSymbolAddress((void**)&als,   g_als);
    cudaGetSymbolAddress((void**)&ald,   g_ald);
    cudaGetSymbolAddress((void**)&den,   g_den);
    cudaGetSymbolAddress((void**)&sums,  g_sums);
    cudaGetSymbolAddress((void**)&sumsq, g_sumsq);

    int blocks128 = (N + 127) / 128;
    int NF = N * FMAX;

    // ================= layer 1: K=128, H=4 =================
    run_split(x, ah, al, N * 128);
    run_split(W1, wh, wl, 256 * 128);
    {
        dim3 g(blocks128, 2);
        gemm_mma<128><<<g, 256>>>(ah, al, wh, wl, h, N, 128, 256);
    }
    logits_kernel<<<(N * 4 + 255) / 256, 256>>>(h, a1s, a1d, als, ald, N, 4);
    run_zero(den, (size_t)N * 4);
    run_zero(acc, (size_t)NF);
    scatter_fused_kernel<<<((size_t)EE * 32 + 255) / 256, 256>>>(ei, E, N, 4, als, ald, h, den, acc);
    zero_stats_kernel<<<1, 256>>>(sums, sumsq);
    finalize_stats_kernel<<<256, 256>>>(acc, den, b1, h, N, sums, sumsq);
    bn_apply_kernel<<<(NF + 255) / 256, 256>>>(h, nullptr, gamma, beta, sums, sumsq, N, res);

    // ================= layer 2: K=256, H=4 =================
    run_split(res, ah, al, N * 256);
    run_split(W2, wh, wl, 256 * 256);
    {
        dim3 g(blocks128, 2);
        gemm_mma<128><<<g, 256>>>(ah, al, wh, wl, h, N, 256, 256);
    }
    logits_kernel<<<(N * 4 + 255) / 256, 256>>>(h, a2s, a2d, als, ald, N, 4);
    run_zero(den, (size_t)N * 4);
    run_zero(acc, (size_t)NF);
    scatter_fused_kernel<<<((size_t)EE * 32 + 255) / 256, 256>>>(ei, E, N, 4, als, ald, h, den, acc);
    zero_stats_kernel<<<1, 256>>>(sums, sumsq);
    finalize_stats_kernel<<<256, 256>>>(acc, den, b2, h, N, sums, sumsq);
    bn_apply_kernel<<<(NF + 255) / 256, 256>>>(h, res, gamma, beta, sums, sumsq, N, acc);

    // ================= layer 3: K=256, H=1 =================
    run_split(acc, ah, al, N * 256);
    run_split(W3, wh, wl, 64 * 256);
    {
        dim3 g(blocks128, 1);
        gemm_mma<64><<<g, 256>>>(ah, al, wh, wl, h, N, 256, 64);
    }
    logits_kernel<<<(N + 255) / 256, 256>>>(h, a3s, a3d, als, ald, N, 1);
    run_zero(den, (size_t)N);
    run_zero(out, (size_t)N * HD);
    scatter_fused_kernel<<<((size_t)EE * 32 + 255) / 256, 256>>>(ei, E, N, 1, als, ald, h, den, out);
    finalize_out_kernel<<<(N * HD + 255) / 256, 256>>>(out, den, b3, N);
}

// round 6
// speedup vs baseline: 1.7334x; 1.7334x over previous
#include <cuda_runtime.h>
#include <cuda_bf16.h>
#include <cstdint>

// ---------------- problem constants ----------------
#define HD   64
#define NHEADS 4
#define NMAX 50000
#define EMAX 400000
#define EEMAX (EMAX + NMAX)
#define FMAX 256

// ---------------- device scratch ----------------
__device__ float g_h[(size_t)NMAX * FMAX];     // gemm output
__device__ float g_acc[(size_t)NMAX * FMAX];   // aggregation output
__device__ float g_res[(size_t)NMAX * FMAX];   // residual
__device__ __nv_bfloat16 g_ah[(size_t)NMAX * FMAX];
__device__ __nv_bfloat16 g_al[(size_t)NMAX * FMAX];
__device__ __nv_bfloat16 g_wh[FMAX * FMAX];
__device__ __nv_bfloat16 g_wl[FMAX * FMAX];
__device__ float g_als[NMAX * NHEADS];
__device__ float g_ald[NMAX * NHEADS];
__device__ float g_sums[FMAX];
__device__ float g_sumsq[FMAX];
// CSR
__device__ int g_counts[NMAX + 1];
__device__ int g_start[NMAX + 1];
__device__ int g_woff[NMAX];
__device__ int g_bsums[256];
__device__ int g_csr_src[EEMAX];

// ---------------- PTX helpers ----------------
__device__ __forceinline__ uint32_t smem_u32(const void* p) {
    uint32_t a;
    asm("{ .reg .u64 t; cvta.to.shared.u64 t, %1; cvt.u32.u64 %0, t; }" : "=r"(a) : "l"(p));
    return a;
}
#define LDMATRIX_X4(R0, R1, R2, R3, ADDR)                                   \
    asm volatile("ldmatrix.sync.aligned.m8n8.x4.shared.b16 {%0,%1,%2,%3}, [%4];" \
                 : "=r"(R0), "=r"(R1), "=r"(R2), "=r"(R3) : "r"(ADDR))
#define MMA_BF16(C, A, B)                                                   \
    asm volatile("mma.sync.aligned.m16n8k16.row.col.f32.bf16.bf16.f32 "     \
                 "{%0,%1,%2,%3}, {%4,%5,%6,%7}, {%8,%9}, {%0,%1,%2,%3};"    \
                 : "+f"((C)[0]), "+f"((C)[1]), "+f"((C)[2]), "+f"((C)[3])   \
                 : "r"((A)[0]), "r"((A)[1]), "r"((A)[2]), "r"((A)[3]),      \
                   "r"((B)[0]), "r"((B)[1]))

// ---------------- fp32 -> bf16 hi/lo split ----------------
__global__ void split_bf16_kernel(const float4* __restrict__ in,
                                  __nv_bfloat162* __restrict__ hi,
                                  __nv_bfloat162* __restrict__ lo, int n4) {
    int i = blockIdx.x * blockDim.x + threadIdx.x;
    if (i >= n4) return;
    float4 v = in[i];
    __nv_bfloat16 h0 = __float2bfloat16(v.x), h1 = __float2bfloat16(v.y);
    __nv_bfloat16 h2 = __float2bfloat16(v.z), h3 = __float2bfloat16(v.w);
    float r0 = v.x - __bfloat162float(h0), r1 = v.y - __bfloat162float(h1);
    float r2 = v.z - __bfloat162float(h2), r3 = v.w - __bfloat162float(h3);
    hi[i * 2 + 0] = __nv_bfloat162(h0, h1);
    hi[i * 2 + 1] = __nv_bfloat162(h2, h3);
    lo[i * 2 + 0] = __nv_bfloat162(__float2bfloat16(r0), __float2bfloat16(r1));
    lo[i * 2 + 1] = __nv_bfloat162(__float2bfloat16(r2), __float2bfloat16(r3));
}

// ---------------- HMMA GEMM, single K-pass over 3 split products ----------------
// C = Ah*Wh^T + Ah*Wl^T + Al*Wh^T. CTA tile 128 x NTILE, 256 threads.
template<int NTILE>
__global__ void __launch_bounds__(256) gemm_mma3(
    const __nv_bfloat16* __restrict__ Ah, const __nv_bfloat16* __restrict__ Al,
    const __nv_bfloat16* __restrict__ Wh, const __nv_bfloat16* __restrict__ Wl,
    float* __restrict__ C, int Nrows, int K, int NOUT) {
    constexpr int RS = 40;
    constexpr int MT = (NTILE == 128) ? 2 : 1;
    constexpr int WN = NTILE / 64;
    __shared__ __nv_bfloat16 AsH[128 * RS];
    __shared__ __nv_bfloat16 AsL[128 * RS];
    __shared__ __nv_bfloat16 WsH[NTILE * RS];
    __shared__ __nv_bfloat16 WsL[NTILE * RS];
    const int tid = threadIdx.x, lane = tid & 31, wid = tid >> 5;
    const int wm = wid / WN, wn = wid % WN;
    const int row0 = blockIdx.x * 128, col0 = blockIdx.y * NTILE;
    const uint32_t ahb = smem_u32(AsH), alb = smem_u32(AsL);
    const uint32_t whb = smem_u32(WsH), wlb = smem_u32(WsL);

    const int a_row  = ((lane >> 3) & 1) * 8 + (lane & 7);
    const int a_koff = ((lane >> 4) & 1) * 8;
    const int b_row  = ((lane >> 4) & 1) * 8 + (lane & 7);
    const int b_koff = ((lane >> 3) & 1) * 8;
    const uint32_t a_off = (uint32_t)(((wm * 16 * MT + a_row) * RS + a_koff) * 2);
    const uint32_t b_off = (uint32_t)(((wn * 64 + b_row) * RS + b_koff) * 2);

    float acc[MT][8][4];
    #pragma unroll
    for (int mt = 0; mt < MT; mt++)
        #pragma unroll
        for (int nt = 0; nt < 8; nt++)
            #pragma unroll
            for (int j = 0; j < 4; j++) acc[mt][nt][j] = 0.f;

    #pragma unroll 1
    for (int k0 = 0; k0 < K; k0 += 32) {
        for (int i = tid; i < 512; i += 256) {
            int r = i >> 2, cv = (i & 3) * 8;
            int gr = row0 + r;
            uint4 vh = make_uint4(0u, 0u, 0u, 0u), vl = vh;
            if (gr < Nrows) {
                vh = *(const uint4*)(Ah + (size_t)gr * K + k0 + cv);
                vl = *(const uint4*)(Al + (size_t)gr * K + k0 + cv);
            }
            *(uint4*)&AsH[r * RS + cv] = vh;
            *(uint4*)&AsL[r * RS + cv] = vl;
        }
        for (int i = tid; i < NTILE * 4; i += 256) {
            int r = i >> 2, cv = (i & 3) * 8;
            *(uint4*)&WsH[r * RS + cv] = *(const uint4*)(Wh + (size_t)(col0 + r) * K + k0 + cv);
            *(uint4*)&WsL[r * RS + cv] = *(const uint4*)(Wl + (size_t)(col0 + r) * K + k0 + cv);
        }
        __syncthreads();
        #pragma unroll
        for (int kk = 0; kk < 32; kk += 16) {
            uint32_t ah_f[MT][4], al_f[MT][4];
            #pragma unroll
            for (int mt = 0; mt < MT; mt++) {
                uint32_t o = a_off + (uint32_t)((mt * 16 * RS + kk) * 2);
                LDMATRIX_X4(ah_f[mt][0], ah_f[mt][1], ah_f[mt][2], ah_f[mt][3], ahb + o);
                LDMATRIX_X4(al_f[mt][0], al_f[mt][1], al_f[mt][2], al_f[mt][3], alb + o);
            }
            uint32_t bh_f[8][2], bl_f[8][2];
            #pragma unroll
            for (int nt16 = 0; nt16 < 4; nt16++) {
                uint32_t o = b_off + (uint32_t)((nt16 * 16 * RS + kk) * 2);
                uint32_t r0, r1, r2, r3;
                LDMATRIX_X4(r0, r1, r2, r3, whb + o);
                bh_f[nt16 * 2 + 0][0] = r0; bh_f[nt16 * 2 + 0][1] = r1;
                bh_f[nt16 * 2 + 1][0] = r2; bh_f[nt16 * 2 + 1][1] = r3;
                LDMATRIX_X4(r0, r1, r2, r3, wlb + o);
                bl_f[nt16 * 2 + 0][0] = r0; bl_f[nt16 * 2 + 0][1] = r1;
                bl_f[nt16 * 2 + 1][0] = r2; bl_f[nt16 * 2 + 1][1] = r3;
            }
            #pragma unroll
            for (int mt = 0; mt < MT; mt++)
                #pragma unroll
                for (int nt = 0; nt < 8; nt++) {
                    MMA_BF16(acc[mt][nt], ah_f[mt], bh_f[nt]);
                    MMA_BF16(acc[mt][nt], ah_f[mt], bl_f[nt]);
                    MMA_BF16(acc[mt][nt], al_f[mt], bh_f[nt]);
                }
        }
        __syncthreads();
    }
    #pragma unroll
    for (int mt = 0; mt < MT; mt++) {
        int mrow = row0 + wm * 16 * MT + mt * 16 + (lane >> 2);
        #pragma unroll
        for (int nt = 0; nt < 8; nt++) {
            int ncol = col0 + wn * 64 + nt * 8 + (lane & 3) * 2;
            if (mrow < Nrows)
                *(float2*)&C[(size_t)mrow * NOUT + ncol] = make_float2(acc[mt][nt][0], acc[mt][nt][1]);
            if (mrow + 8 < Nrows)
                *(float2*)&C[(size_t)(mrow + 8) * NOUT + ncol] = make_float2(acc[mt][nt][2], acc[mt][nt][3]);
        }
    }
}

// ---------------- logits: warp per (node, head), coalesced ----------------
__global__ void logits_warp_kernel(const float* __restrict__ h,
                                   const float* __restrict__ a_s, const float* __restrict__ a_d,
                                   float* __restrict__ als, float* __restrict__ ald,
                                   int NH, int Hh) {
    int idx = (blockIdx.x * blockDim.x + threadIdx.x) >> 5;
    int lane = threadIdx.x & 31;
    if (idx >= NH) return;
    int n = idx / Hh, hh = idx - n * Hh;
    float2 v = ((const float2*)(h + (size_t)n * Hh * HD + hh * HD))[lane];
    float2 s2 = ((const float2*)(a_s + hh * HD))[lane];
    float2 d2 = ((const float2*)(a_d + hh * HD))[lane];
    float ss = v.x * s2.x + v.y * s2.y;
    float sd = v.x * d2.x + v.y * d2.y;
    #pragma unroll
    for (int o = 16; o > 0; o >>= 1) {
        ss += __shfl_xor_sync(0xffffffff, ss, o);
        sd += __shfl_xor_sync(0xffffffff, sd, o);
    }
    if (lane == 0) { als[idx] = ss; ald[idx] = sd; }
}

// ---------------- CSR build ----------------
__global__ void zero_int_kernel(int* __restrict__ p, int n) {
    int i = blockIdx.x * blockDim.x + threadIdx.x;
    if (i < n) p[i] = 0;
}
__global__ void count_kernel(const int* __restrict__ ei, int E, int N, int* __restrict__ cnt) {
    int e = blockIdx.x * blockDim.x + threadIdx.x;
    int EE = E + N;
    if (e >= EE) return;
    int d = (e < E) ? ei[E + e] : e - E;
    atomicAdd(&cnt[d], 1);
}
__global__ void scan_block_kernel(const int* __restrict__ cnt, int* __restrict__ excl,
                                  int* __restrict__ bsums, int N) {
    __shared__ int sh[256];
    int tid = threadIdx.x;
    int i = blockIdx.x * 256 + tid;
    int v = (i < N) ? cnt[i] : 0;
    sh[tid] = v;
    __syncthreads();
    #pragma unroll
    for (int off = 1; off < 256; off <<= 1) {
        int t = (tid >= off) ? sh[tid - off] : 0;
        __syncthreads();
        sh[tid] += t;
        __syncthreads();
    }
    if (i < N) excl[i] = sh[tid] - v;
    if (tid == 255) bsums[blockIdx.x] = sh[255];
}
__global__ void scan_sums_kernel(int* __restrict__ bsums, int nb) {
    __shared__ int sh[256];
    int tid = threadIdx.x;
    int v = (tid < nb) ? bsums[tid] : 0;
    sh[tid] = v;
    __syncthreads();
    #pragma unroll
    for (int off = 1; off < 256; off <<= 1) {
        int t = (tid >= off) ? sh[tid - off] : 0;
        __syncthreads();
        sh[tid] += t;
        __syncthreads();
    }
    if (tid < nb) bsums[tid] = sh[tid] - v;  // exclusive
}
__global__ void add_offsets_kernel(int* __restrict__ excl, const int* __restrict__ bsums,
                                   int* __restrict__ woff, int N, int EE) {
    int i = blockIdx.x * 256 + threadIdx.x;
    if (i < N) {
        int v = excl[i] + bsums[blockIdx.x];
        excl[i] = v;
        woff[i] = v;
    }
    if (blockIdx.x == 0 && threadIdx.x == 0) excl[N] = EE;
}
__global__ void fill_kernel(const int* __restrict__ ei, int E, int N,
                            int* __restrict__ woff, int* __restrict__ csr_src) {
    int e = blockIdx.x * blockDim.x + threadIdx.x;
    int EE = E + N;
    if (e >= EE) return;
    int s, d;
    if (e < E) { s = ei[e]; d = ei[E + e]; }
    else       { s = d = e - E; }
    int pos = atomicAdd(&woff[d], 1);
    csr_src[pos] = s;
}

// ---------------- CSR aggregation: warp per dst node, no atomics ----------------
template<int Hh>
__global__ void __launch_bounds__(256) agg_kernel(
    const int* __restrict__ start, const int* __restrict__ csr_src,
    const float* __restrict__ als, const float* __restrict__ ald,
    const float* __restrict__ h, const float* __restrict__ bias,
    float* __restrict__ out, int N,
    float* __restrict__ sums, float* __restrict__ sumsq, int do_stats) {
    constexpr int F = Hh * HD;
    __shared__ float s_s[256], s_q[256];
    int tid = threadIdx.x, lane = tid & 31, wid = tid >> 5;
    if (do_stats) { s_s[tid] = 0.f; s_q[tid] = 0.f; __syncthreads(); }
    int d = blockIdx.x * 8 + wid;
    if (d < N) {
        float aldv[Hh], den[Hh];
        #pragma unroll
        for (int hh = 0; hh < Hh; hh++) { aldv[hh] = ald[d * Hh + hh]; den[hh] = 0.f; }
        float4 acc0 = make_float4(0.f, 0.f, 0.f, 0.f);
        float4 acc1 = make_float4(0.f, 0.f, 0.f, 0.f);
        const float4* h4 = (const float4*)h;
        int j1 = start[d + 1];
        for (int j = start[d]; j < j1; j++) {
            int s = csr_src[j];
            float ev[Hh];
            #pragma unroll
            for (int hh = 0; hh < Hh; hh++) {
                float v = als[s * Hh + hh] + aldv[hh];
                v = v > 0.f ? v : 0.2f * v;
                ev[hh] = __expf(v);
                den[hh] += ev[hh];
            }
            const float4* hr = h4 + (size_t)s * (F / 4);
            if (Hh == 4) {
                float e0 = (lane < 16) ? ev[0] : ev[1];
                float e1 = (lane < 16) ? ev[2] : ev[3];
                float4 v0 = hr[lane];
                float4 v1 = hr[lane + 32];
                acc0.x += e0 * v0.x; acc0.y += e0 * v0.y; acc0.z += e0 * v0.z; acc0.w += e0 * v0.w;
                acc1.x += e1 * v1.x; acc1.y += e1 * v1.y; acc1.z += e1 * v1.z; acc1.w += e1 * v1.w;
            } else {
                if (lane < 16) {
                    float4 v0 = hr[lane];
                    acc0.x += ev[0] * v0.x; acc0.y += ev[0] * v0.y;
                    acc0.z += ev[0] * v0.z; acc0.w += ev[0] * v0.w;
                }
            }
        }
        const float4* b4 = (const float4*)bias;
        float4* o4 = (float4*)(out + (size_t)d * F);
        if (Hh == 4) {
            float i0 = 1.f / ((lane < 16) ? den[0] : den[1]);
            float i1 = 1.f / ((lane < 16) ? den[2] : den[3]);
            float4 bb0 = b4[lane], bb1 = b4[lane + 32];
            float4 r0 = make_float4(acc0.x * i0 + bb0.x, acc0.y * i0 + bb0.y,
                                    acc0.z * i0 + bb0.z, acc0.w * i0 + bb0.w);
            float4 r1 = make_float4(acc1.x * i1 + bb1.x, acc1.y * i1 + bb1.y,
                                    acc1.z * i1 + bb1.z, acc1.w * i1 + bb1.w);
            o4[lane] = r0;
            o4[lane + 32] = r1;
            if (do_stats) {
                int f0 = lane * 4, f1 = (lane + 32) * 4;
                atomicAdd(&s_s[f0 + 0], r0.x); atomicAdd(&s_q[f0 + 0], r0.x * r0.x);
                atomicAdd(&s_s[f0 + 1], r0.y); atomicAdd(&s_q[f0 + 1], r0.y * r0.y);
                atomicAdd(&s_s[f0 + 2], r0.z); atomicAdd(&s_q[f0 + 2], r0.z * r0.z);
                atomicAdd(&s_s[f0 + 3], r0.w); atomicAdd(&s_q[f0 + 3], r0.w * r0.w);
                atomicAdd(&s_s[f1 + 0], r1.x); atomicAdd(&s_q[f1 + 0], r1.x * r1.x);
                atomicAdd(&s_s[f1 + 1], r1.y); atomicAdd(&s_q[f1 + 1], r1.y * r1.y);
                atomicAdd(&s_s[f1 + 2], r1.z); atomicAdd(&s_q[f1 + 2], r1.z * r1.z);
                atomicAdd(&s_s[f1 + 3], r1.w); atomicAdd(&s_q[f1 + 3], r1.w * r1.w);
            }
        } else {
            if (lane < 16) {
                float i0 = 1.f / den[0];
                float4 bb = b4[lane];
                o4[lane] = make_float4(acc0.x * i0 + bb.x, acc0.y * i0 + bb.y,
                                       acc0.z * i0 + bb.z, acc0.w * i0 + bb.w);
            }
        }
    }
    if (do_stats) {
        __syncthreads();
        atomicAdd(&sums[tid], s_s[tid]);
        atomicAdd(&sumsq[tid], s_q[tid]);
    }
}

__global__ void zero_stats_kernel(float* __restrict__ s, float* __restrict__ s2) {
    s[threadIdx.x] = 0.f;
    s2[threadIdx.x] = 0.f;
}

// ---------------- BN + leakyReLU (+res) fused with bf16 split ----------------
__global__ void bn_split_kernel(const float4* __restrict__ x, const float4* __restrict__ res_in,
                                const float4* __restrict__ gamma4, const float4* __restrict__ beta4,
                                const float4* __restrict__ sums4, const float4* __restrict__ sumsq4,
                                float invn, int n4, float4* __restrict__ res_out,
                                __nv_bfloat162* __restrict__ hi, __nv_bfloat162* __restrict__ lo) {
    int i = blockIdx.x * blockDim.x + threadIdx.x;
    if (i >= n4) return;
    int f4 = i & 63;
    float4 xv = x[i], g = gamma4[f4], b = beta4[f4], s = sums4[f4], q = sumsq4[f4];
    float4 v;
    {
        float mu = s.x * invn, var = q.x * invn - mu * mu;
        v.x = g.x * (xv.x - mu) * rsqrtf(var + 1e-5f) + b.x;
        mu = s.y * invn; var = q.y * invn - mu * mu;
        v.y = g.y * (xv.y - mu) * rsqrtf(var + 1e-5f) + b.y;
        mu = s.z * invn; var = q.z * invn - mu * mu;
        v.z = g.z * (xv.z - mu) * rsqrtf(var + 1e-5f) + b.z;
        mu = s.w * invn; var = q.w * invn - mu * mu;
        v.w = g.w * (xv.w - mu) * rsqrtf(var + 1e-5f) + b.w;
    }
    v.x = v.x > 0.f ? v.x : 0.01f * v.x;
    v.y = v.y > 0.f ? v.y : 0.01f * v.y;
    v.z = v.z > 0.f ? v.z : 0.01f * v.z;
    v.w = v.w > 0.f ? v.w : 0.01f * v.w;
    if (res_in) {
        float4 r = res_in[i];
        v.x += r.x; v.y += r.y; v.z += r.z; v.w += r.w;
    }
    if (res_out) res_out[i] = v;
    __nv_bfloat16 h0 = __float2bfloat16(v.x), h1 = __float2bfloat16(v.y);
    __nv_bfloat16 h2 = __float2bfloat16(v.z), h3 = __float2bfloat16(v.w);
    hi[i * 2 + 0] = __nv_bfloat162(h0, h1);
    hi[i * 2 + 1] = __nv_bfloat162(h2, h3);
    lo[i * 2 + 0] = __nv_bfloat162(__float2bfloat16(v.x - __bfloat162float(h0)),
                                   __float2bfloat16(v.y - __bfloat162float(h1)));
    lo[i * 2 + 1] = __nv_bfloat162(__float2bfloat16(v.z - __bfloat162float(h2)),
                                   __float2bfloat16(v.w - __bfloat162float(h3)));
}

// ---------------- host ----------------
static void run_split(const float* in, __nv_bfloat16* hi, __nv_bfloat16* lo, int n) {
    int n4 = n / 4;
    split_bf16_kernel<<<(n4 + 255) / 256, 256>>>((const float4*)in,
                                                 (__nv_bfloat162*)hi, (__nv_bfloat162*)lo, n4);
}

extern "C" void kernel_launch(void* const* d_in, const int* in_sizes, int n_in,
                              void* d_out, int out_size) {
    const float* x     = (const float*)d_in[0];
    const int*   ei    = (const int*)d_in[1];
    const float* W1    = (const float*)d_in[2];
    const float* a1s   = (const float*)d_in[3];
    const float* a1d   = (const float*)d_in[4];
    const float* b1    = (const float*)d_in[5];
    const float* W2    = (const float*)d_in[6];
    const float* a2s   = (const float*)d_in[7];
    const float* a2d   = (const float*)d_in[8];
    const float* b2    = (const float*)d_in[9];
    const float* W3    = (const float*)d_in[10];
    const float* a3s   = (const float*)d_in[11];
    const float* a3d   = (const float*)d_in[12];
    const float* b3    = (const float*)d_in[13];
    const float* gamma = (const float*)d_in[14];
    const float* beta  = (const float*)d_in[15];
    float* out = (float*)d_out;

    int N = in_sizes[0] / (2 * HD);
    int E = in_sizes[1] / 2;
    int EE = E + N;

    float *h, *acc, *res, *als, *ald, *sums, *sumsq;
    __nv_bfloat16 *ah, *al, *wh, *wl;
    int *counts, *start, *woff, *bsums, *csr_src;
    cudaGetSymbolAddress((void**)&h,       g_h);
    cudaGetSymbolAddress((void**)&acc,     g_acc);
    cudaGetSymbolAddress((void**)&res,     g_res);
    cudaGetSymbolAddress((void**)&ah,      g_ah);
    cudaGetSymbolAddress((void**)&al,      g_al);
    cudaGetSymbolAddress((void**)&wh,      g_wh);
    cudaGetSymbolAddress((void**)&wl,      g_wl);
    cudaGetSymbolAddress((void**)&als,     g_als);
    cudaGetSymbolAddress((void**)&ald,     g_ald);
    cudaGetSymbolAddress((void**)&sums,    g_sums);
    cudaGetSymbolAddress((void**)&sumsq,   g_sumsq);
    cudaGetSymbolAddress((void**)&counts,  g_counts);
    cudaGetSymbolAddress((void**)&start,   g_start);
    cudaGetSymbolAddress((void**)&woff,    g_woff);
    cudaGetSymbolAddress((void**)&bsums,   g_bsums);
    cudaGetSymbolAddress((void**)&csr_src, g_csr_src);

    int blocks128 = (N + 127) / 128;
    int nb = (N + 255) / 256;

    // ---- CSR build (reused by all 3 layers) ----
    zero_int_kernel<<<nb, 256>>>(counts, N);
    count_kernel<<<(EE + 255) / 256, 256>>>(ei, E, N, counts);
    scan_block_kernel<<<nb, 256>>>(counts, start, bsums, N);
    scan_sums_kernel<<<1, 256>>>(bsums, nb);
    add_offsets_kernel<<<nb, 256>>>(start, bsums, woff, N, EE);
    fill_kernel<<<(EE + 255) / 256, 256>>>(ei, E, N, woff, csr_src);

    int lw_grid4 = (N * 4 * 32 + 255) / 256;
    int lw_grid1 = (N * 32 + 255) / 256;
    int agg_grid = (N + 7) / 8;
    int n4 = N * 64;

    // ================= layer 1: K=128, H=4 =================
    run_split(x, ah, al, N * 128);
    run_split(W1, wh, wl, 256 * 128);
    gemm_mma3<128><<<dim3(blocks128, 2), 256>>>(ah, al, wh, wl, h, N, 128, 256);
    logits_warp_kernel<<<lw_grid4, 256>>>(h, a1s, a1d, als, ald, N * 4, 4);
    zero_stats_kernel<<<1, 256>>>(sums, sumsq);
    agg_kernel<4><<<agg_grid, 256>>>(start, csr_src, als, ald, h, b1, acc, N, sums, sumsq, 1);
    bn_split_kernel<<<(n4 + 255) / 256, 256>>>((const float4*)acc, nullptr,
        (const float4*)gamma, (const float4*)beta, (const float4*)sums, (const float4*)sumsq,
        1.0f / (float)N, n4, (float4*)res, (__nv_bfloat162*)ah, (__nv_bfloat162*)al);

    // ================= layer 2: K=256, H=4 =================
    run_split(W2, wh, wl, 256 * 256);
    gemm_mma3<128><<<dim3(blocks128, 2), 256>>>(ah, al, wh, wl, h, N, 256, 256);
    logits_warp_kernel<<<lw_grid4, 256>>>(h, a2s, a2d, als, ald, N * 4, 4);
    zero_stats_kernel<<<1, 256>>>(sums, sumsq);
    agg_kernel<4><<<agg_grid, 256>>>(start, csr_src, als, ald, h, b2, acc, N, sums, sumsq, 1);
    bn_split_kernel<<<(n4 + 255) / 256, 256>>>((const float4*)acc, (const float4*)res,
        (const float4*)gamma, (const float4*)beta, (const float4*)sums, (const float4*)sumsq,
        1.0f / (float)N, n4, nullptr, (__nv_bfloat162*)ah, (__nv_bfloat162*)al);

    // ================= layer 3: K=256, H=1 =================
    run_split(W3, wh, wl, 64 * 256);
    gemm_mma3<64><<<dim3(blocks128, 1), 256>>>(ah, al, wh, wl, h, N, 256, 64);
    logits_warp_kernel<<<lw_grid1, 256>>>(h, a3s, a3d, als, ald, N, 1);
    agg_kernel<1><<<agg_grid, 256>>>(start, csr_src, als, ald, h, b3, out, N, sums, sumsq, 0);
}

// round 7
// speedup vs baseline: 1.7816x; 1.0278x over previous
#include <cuda_runtime.h>
#include <cuda_bf16.h>
#include <cstdint>

// ---------------- problem constants ----------------
#define HD   64
#define NHEADS 4
#define NMAX 50000
#define EMAX 400000
#define EEMAX (EMAX + NMAX)
#define FMAX 256

// ---------------- device scratch ----------------
__device__ float g_h[(size_t)NMAX * FMAX];     // gemm output
__device__ float g_acc[(size_t)NMAX * FMAX];   // aggregation output
__device__ float g_res[(size_t)NMAX * FMAX];   // residual
__device__ __nv_bfloat16 g_ah[(size_t)NMAX * FMAX];
__device__ __nv_bfloat16 g_al[(size_t)NMAX * FMAX];
__device__ __nv_bfloat16 g_wh[FMAX * FMAX];
__device__ __nv_bfloat16 g_wl[FMAX * FMAX];
__device__ float g_als[NMAX * NHEADS];
__device__ float g_ald[NMAX * NHEADS];
__device__ float g_sums[FMAX];
__device__ float g_sumsq[FMAX];
// CSR
__device__ int g_counts[NMAX + 1];
__device__ int g_start[NMAX + 1];
__device__ int g_woff[NMAX];
__device__ int g_bsums[256];
__device__ int g_csr_src[EEMAX];

// ---------------- PTX helpers ----------------
__device__ __forceinline__ uint32_t smem_u32(const void* p) {
    uint32_t a;
    asm("{ .reg .u64 t; cvta.to.shared.u64 t, %1; cvt.u32.u64 %0, t; }" : "=r"(a) : "l"(p));
    return a;
}
__device__ __forceinline__ void cp16(uint32_t dst, const void* src) {
    asm volatile("cp.async.cg.shared.global [%0], [%1], 16;" :: "r"(dst), "l"(src));
}
#define CP_COMMIT() asm volatile("cp.async.commit_group;" ::: "memory")
#define LDMATRIX_X4(R0, R1, R2, R3, ADDR)                                   \
    asm volatile("ldmatrix.sync.aligned.m8n8.x4.shared.b16 {%0,%1,%2,%3}, [%4];" \
                 : "=r"(R0), "=r"(R1), "=r"(R2), "=r"(R3) : "r"(ADDR))
#define MMA_BF16(C, A, B)                                                   \
    asm volatile("mma.sync.aligned.m16n8k16.row.col.f32.bf16.bf16.f32 "     \
                 "{%0,%1,%2,%3}, {%4,%5,%6,%7}, {%8,%9}, {%0,%1,%2,%3};"    \
                 : "+f"((C)[0]), "+f"((C)[1]), "+f"((C)[2]), "+f"((C)[3])   \
                 : "r"((A)[0]), "r"((A)[1]), "r"((A)[2]), "r"((A)[3]),      \
                   "r"((B)[0]), "r"((B)[1]))

__device__ __forceinline__ float expw(float v) {
    v = v > 0.f ? v : 0.2f * v;
    return __expf(v);
}

// ---------------- fp32 -> bf16 hi/lo split ----------------
__global__ void split_bf16_kernel(const float4* __restrict__ in,
                                  __nv_bfloat162* __restrict__ hi,
                                  __nv_bfloat162* __restrict__ lo, int n4) {
    int i = blockIdx.x * blockDim.x + threadIdx.x;
    if (i >= n4) return;
    float4 v = in[i];
    __nv_bfloat16 h0 = __float2bfloat16(v.x), h1 = __float2bfloat16(v.y);
    __nv_bfloat16 h2 = __float2bfloat16(v.z), h3 = __float2bfloat16(v.w);
    hi[i * 2 + 0] = __nv_bfloat162(h0, h1);
    hi[i * 2 + 1] = __nv_bfloat162(h2, h3);
    lo[i * 2 + 0] = __nv_bfloat162(__float2bfloat16(v.x - __bfloat162float(h0)),
                                   __float2bfloat16(v.y - __bfloat162float(h1)));
    lo[i * 2 + 1] = __nv_bfloat162(__float2bfloat16(v.z - __bfloat162float(h2)),
                                   __float2bfloat16(v.w - __bfloat162float(h3)));
}

// ---------------- HMMA GEMM, cp.async double-buffered, 3 split products ----------------
// C = Ah*Wh^T + Ah*Wl^T + Al*Wh^T. CTA tile 128 x NTILE, 256 threads.
template<int NTILE>
__global__ void __launch_bounds__(256) gemm_mma3(
    const __nv_bfloat16* __restrict__ Ah, const __nv_bfloat16* __restrict__ Al,
    const __nv_bfloat16* __restrict__ Wh, const __nv_bfloat16* __restrict__ Wl,
    float* __restrict__ C, int Nrows, int K, int NOUT) {
    constexpr int RS = 40;                         // smem row stride (bf16)
    constexpr int MT = (NTILE == 128) ? 2 : 1;
    constexpr int WN = NTILE / 64;
    constexpr int A_BYTES = 128 * RS * 2;          // 10240
    constexpr int W_BYTES = NTILE * RS * 2;
    constexpr int STAGE = 2 * A_BYTES + 2 * W_BYTES;
    extern __shared__ char dsm[];
    const uint32_t sbase = smem_u32(dsm);
    const int tid = threadIdx.x, lane = tid & 31, wid = tid >> 5;
    const int wm = wid / WN, wn = wid % WN;
    const int row0 = blockIdx.x * 128, col0 = blockIdx.y * NTILE;

    const int a_row  = ((lane >> 3) & 1) * 8 + (lane & 7);
    const int a_koff = ((lane >> 4) & 1) * 8;
    const int b_row  = ((lane >> 4) & 1) * 8 + (lane & 7);
    const int b_koff = ((lane >> 3) & 1) * 8;
    const uint32_t a_off = (uint32_t)(((wm * 16 * MT + a_row) * RS + a_koff) * 2);
    const uint32_t b_off = (uint32_t)(((wn * 64 + b_row) * RS + b_koff) * 2);

    float acc[MT][8][4];
    #pragma unroll
    for (int mt = 0; mt < MT; mt++)
        #pragma unroll
        for (int nt = 0; nt < 8; nt++)
            #pragma unroll
            for (int j = 0; j < 4; j++) acc[mt][nt][j] = 0.f;

    const int nchunks = K >> 5;

    // ---- issue chunk loader (macro-style inline) ----
    auto issue_chunk = [&](int ck) {
        const int st = ck & 1;
        const uint32_t ah_s = sbase + st * STAGE;
        const uint32_t al_s = ah_s + A_BYTES;
        const uint32_t wh_s = al_s + A_BYTES;
        const uint32_t wl_s = wh_s + W_BYTES;
        const int k0 = ck << 5;
        #pragma unroll 2
        for (int i = tid; i < 512; i += 256) {
            int r = i >> 2, c16 = i & 3;
            int gr = row0 + r;
            if (gr >= Nrows) gr = Nrows - 1;   // clamp: garbage rows never stored
            const char* pa = (const char*)(Ah + (size_t)gr * K + k0) + c16 * 16;
            const char* pl = (const char*)(Al + (size_t)gr * K + k0) + c16 * 16;
            uint32_t dof = (uint32_t)(r * RS + c16 * 8) * 2;
            cp16(ah_s + dof, pa);
            cp16(al_s + dof, pl);
        }
        #pragma unroll 2
        for (int i = tid; i < NTILE * 4; i += 256) {
            int r = i >> 2, c16 = i & 3;
            const char* pw = (const char*)(Wh + (size_t)(col0 + r) * K + k0) + c16 * 16;
            const char* pv = (const char*)(Wl + (size_t)(col0 + r) * K + k0) + c16 * 16;
            uint32_t dof = (uint32_t)(r * RS + c16 * 8) * 2;
            cp16(wh_s + dof, pw);
            cp16(wl_s + dof, pv);
        }
        CP_COMMIT();
    };

    issue_chunk(0);
    for (int ck = 0; ck < nchunks; ck++) {
        if (ck + 1 < nchunks) {
            issue_chunk(ck + 1);
            asm volatile("cp.async.wait_group 1;" ::: "memory");
        } else {
            asm volatile("cp.async.wait_group 0;" ::: "memory");
        }
        __syncthreads();
        const int st = ck & 1;
        const uint32_t ahb = sbase + st * STAGE;
        const uint32_t alb = ahb + A_BYTES;
        const uint32_t whb = alb + A_BYTES;
        const uint32_t wlb = whb + W_BYTES;
        #pragma unroll
        for (int kk = 0; kk < 32; kk += 16) {
            uint32_t ah_f[MT][4], al_f[MT][4];
            #pragma unroll
            for (int mt = 0; mt < MT; mt++) {
                uint32_t o = a_off + (uint32_t)((mt * 16 * RS + kk) * 2);
                LDMATRIX_X4(ah_f[mt][0], ah_f[mt][1], ah_f[mt][2], ah_f[mt][3], ahb + o);
                LDMATRIX_X4(al_f[mt][0], al_f[mt][1], al_f[mt][2], al_f[mt][3], alb + o);
            }
            uint32_t bh_f[8][2], bl_f[8][2];
            #pragma unroll
            for (int nt16 = 0; nt16 < 4; nt16++) {
                uint32_t o = b_off + (uint32_t)((nt16 * 16 * RS + kk) * 2);
                uint32_t r0, r1, r2, r3;
                LDMATRIX_X4(r0, r1, r2, r3, whb + o);
                bh_f[nt16 * 2 + 0][0] = r0; bh_f[nt16 * 2 + 0][1] = r1;
                bh_f[nt16 * 2 + 1][0] = r2; bh_f[nt16 * 2 + 1][1] = r3;
                LDMATRIX_X4(r0, r1, r2, r3, wlb + o);
                bl_f[nt16 * 2 + 0][0] = r0; bl_f[nt16 * 2 + 0][1] = r1;
                bl_f[nt16 * 2 + 1][0] = r2; bl_f[nt16 * 2 + 1][1] = r3;
            }
            #pragma unroll
            for (int mt = 0; mt < MT; mt++)
                #pragma unroll
                for (int nt = 0; nt < 8; nt++) {
                    MMA_BF16(acc[mt][nt], ah_f[mt], bh_f[nt]);
                    MMA_BF16(acc[mt][nt], ah_f[mt], bl_f[nt]);
                    MMA_BF16(acc[mt][nt], al_f[mt], bh_f[nt]);
                }
        }
        __syncthreads();
    }
    #pragma unroll
    for (int mt = 0; mt < MT; mt++) {
        int mrow = row0 + wm * 16 * MT + mt * 16 + (lane >> 2);
        #pragma unroll
        for (int nt = 0; nt < 8; nt++) {
            int ncol = col0 + wn * 64 + nt * 8 + (lane & 3) * 2;
            if (mrow < Nrows)
                *(float2*)&C[(size_t)mrow * NOUT + ncol] = make_float2(acc[mt][nt][0], acc[mt][nt][1]);
            if (mrow + 8 < Nrows)
                *(float2*)&C[(size_t)(mrow + 8) * NOUT + ncol] = make_float2(acc[mt][nt][2], acc[mt][nt][3]);
        }
    }
}

// ---------------- logits: warp per (node, head), coalesced ----------------
__global__ void logits_warp_kernel(const float* __restrict__ h,
                                   const float* __restrict__ a_s, const float* __restrict__ a_d,
                                   float* __restrict__ als, float* __restrict__ ald,
                                   int NH, int Hh) {
    int idx = (blockIdx.x * blockDim.x + threadIdx.x) >> 5;
    int lane = threadIdx.x & 31;
    if (idx >= NH) return;
    int n = idx / Hh, hh = idx - n * Hh;
    float2 v = ((const float2*)(h + (size_t)n * Hh * HD + hh * HD))[lane];
    float2 s2 = ((const float2*)(a_s + hh * HD))[lane];
    float2 d2 = ((const float2*)(a_d + hh * HD))[lane];
    float ss = v.x * s2.x + v.y * s2.y;
    float sd = v.x * d2.x + v.y * d2.y;
    #pragma unroll
    for (int o = 16; o > 0; o >>= 1) {
        ss += __shfl_xor_sync(0xffffffff, ss, o);
        sd += __shfl_xor_sync(0xffffffff, sd, o);
    }
    if (lane == 0) { als[idx] = ss; ald[idx] = sd; }
}

// ---------------- CSR build ----------------
__global__ void zero_int_kernel(int* __restrict__ p, int n) {
    int i = blockIdx.x * blockDim.x + threadIdx.x;
    if (i < n) p[i] = 0;
}
__global__ void count_kernel(const int* __restrict__ ei, int E, int N, int* __restrict__ cnt) {
    int e = blockIdx.x * blockDim.x + threadIdx.x;
    int EE = E + N;
    if (e >= EE) return;
    int d = (e < E) ? ei[E + e] : e - E;
    atomicAdd(&cnt[d], 1);
}
__global__ void scan_block_kernel(const int* __restrict__ cnt, int* __restrict__ excl,
                                  int* __restrict__ bsums, int N) {
    __shared__ int sh[256];
    int tid = threadIdx.x;
    int i = blockIdx.x * 256 + tid;
    int v = (i < N) ? cnt[i] : 0;
    sh[tid] = v;
    __syncthreads();
    #pragma unroll
    for (int off = 1; off < 256; off <<= 1) {
        int t = (tid >= off) ? sh[tid - off] : 0;
        __syncthreads();
        sh[tid] += t;
        __syncthreads();
    }
    if (i < N) excl[i] = sh[tid] - v;
    if (tid == 255) bsums[blockIdx.x] = sh[255];
}
__global__ void scan_sums_kernel(int* __restrict__ bsums, int nb) {
    __shared__ int sh[256];
    int tid = threadIdx.x;
    int v = (tid < nb) ? bsums[tid] : 0;
    sh[tid] = v;
    __syncthreads();
    #pragma unroll
    for (int off = 1; off < 256; off <<= 1) {
        int t = (tid >= off) ? sh[tid - off] : 0;
        __syncthreads();
        sh[tid] += t;
        __syncthreads();
    }
    if (tid < nb) bsums[tid] = sh[tid] - v;  // exclusive
}
__global__ void add_offsets_kernel(int* __restrict__ excl, const int* __restrict__ bsums,
                                   int* __restrict__ woff, int N, int EE) {
    int i = blockIdx.x * 256 + threadIdx.x;
    if (i < N) {
        int v = excl[i] + bsums[blockIdx.x];
        excl[i] = v;
        woff[i] = v;
    }
    if (blockIdx.x == 0 && threadIdx.x == 0) excl[N] = EE;
}
__global__ void fill_kernel(const int* __restrict__ ei, int E, int N,
                            int* __restrict__ woff, int* __restrict__ csr_src) {
    int e = blockIdx.x * blockDim.x + threadIdx.x;
    int EE = E + N;
    if (e >= EE) return;
    int s, d;
    if (e < E) { s = ei[e]; d = ei[E + e]; }
    else       { s = d = e - E; }
    int pos = atomicAdd(&woff[d], 1);
    csr_src[pos] = s;
}

// ---------------- CSR aggregation, H=4: 2 warps per dst (feature halves) ----------------
__global__ void __launch_bounds__(256) agg4_kernel(
    const int* __restrict__ start, const int* __restrict__ csr_src,
    const float* __restrict__ als, const float* __restrict__ ald,
    const float* __restrict__ h, const float* __restrict__ bias,
    float* __restrict__ out, int N,
    float* __restrict__ sums, float* __restrict__ sumsq, int do_stats) {
    __shared__ float s_s[256], s_q[256];
    int tid = threadIdx.x, lane = tid & 31, wid = tid >> 5;
    if (do_stats) { s_s[tid] = 0.f; s_q[tid] = 0.f; __syncthreads(); }
    int d = blockIdx.x * 4 + (wid >> 1);
    int half = wid & 1;
    if (d < N) {
        const float2* als2 = (const float2*)als;
        float2 aldv = ((const float2*)ald)[d * 2 + half];  // heads 2*half, 2*half+1
        float den0 = 0.f, den1 = 0.f;
        float4 acc = make_float4(0.f, 0.f, 0.f, 0.f);
        const float4* h4 = (const float4*)h;
        int c4 = half * 32 + lane;
        int j0 = start[d], j1 = start[d + 1];
        int j = j0;
        for (; j + 2 <= j1; j += 2) {
            int s0 = csr_src[j], s1 = csr_src[j + 1];
            float2 a0 = als2[s0 * 2 + half];
            float2 a1 = als2[s1 * 2 + half];
            float4 v0 = h4[(size_t)s0 * 64 + c4];
            float4 v1 = h4[(size_t)s1 * 64 + c4];
            float e00 = expw(a0.x + aldv.x), e01 = expw(a0.y + aldv.y);
            float e10 = expw(a1.x + aldv.x), e11 = expw(a1.y + aldv.y);
            den0 += e00 + e10;
            den1 += e01 + e11;
            float w0 = (lane < 16) ? e00 : e01;
            float w1 = (lane < 16) ? e10 : e11;
            acc.x += w0 * v0.x + w1 * v1.x;
            acc.y += w0 * v0.y + w1 * v1.y;
            acc.z += w0 * v0.z + w1 * v1.z;
            acc.w += w0 * v0.w + w1 * v1.w;
        }
        if (j < j1) {
            int s0 = csr_src[j];
            float2 a0 = als2[s0 * 2 + half];
            float4 v0 = h4[(size_t)s0 * 64 + c4];
            float e00 = expw(a0.x + aldv.x), e01 = expw(a0.y + aldv.y);
            den0 += e00;
            den1 += e01;
            float w0 = (lane < 16) ? e00 : e01;
            acc.x += w0 * v0.x; acc.y += w0 * v0.y;
            acc.z += w0 * v0.z; acc.w += w0 * v0.w;
        }
        float inv = 1.f / ((lane < 16) ? den0 : den1);
        float4 bb = ((const float4*)bias)[c4];
        float4 r = make_float4(acc.x * inv + bb.x, acc.y * inv + bb.y,
                               acc.z * inv + bb.z, acc.w * inv + bb.w);
        ((float4*)(out + (size_t)d * 256))[c4] = r;
        if (do_stats) {
            int f = c4 * 4;
            atomicAdd(&s_s[f + 0], r.x); atomicAdd(&s_q[f + 0], r.x * r.x);
            atomicAdd(&s_s[f + 1], r.y); atomicAdd(&s_q[f + 1], r.y * r.y);
            atomicAdd(&s_s[f + 2], r.z); atomicAdd(&s_q[f + 2], r.z * r.z);
            atomicAdd(&s_s[f + 3], r.w); atomicAdd(&s_q[f + 3], r.w * r.w);
        }
    }
    if (do_stats) {
        __syncthreads();
        atomicAdd(&sums[tid], s_s[tid]);
        atomicAdd(&sumsq[tid], s_q[tid]);
    }
}

// ---------------- CSR aggregation, H=1 (F=64): warp per dst, float2/lane ----------------
__global__ void __launch_bounds__(256) agg1_kernel(
    const int* __restrict__ start, const int* __restrict__ csr_src,
    const float* __restrict__ als, const float* __restrict__ ald,
    const float* __restrict__ h, const float* __restrict__ bias,
    float* __restrict__ out, int N) {
    int tid = threadIdx.x, lane = tid & 31, wid = tid >> 5;
    int d = blockIdx.x * 8 + wid;
    if (d >= N) return;
    float aldv = ald[d];
    float den = 0.f;
    float2 acc = make_float2(0.f, 0.f);
    const float2* h2 = (const float2*)h;
    int j0 = start[d], j1 = start[d + 1];
    int j = j0;
    for (; j + 2 <= j1; j += 2) {
        int s0 = csr_src[j], s1 = csr_src[j + 1];
        float a0 = als[s0], a1 = als[s1];
        float2 v0 = h2[(size_t)s0 * 32 + lane];
        float2 v1 = h2[(size_t)s1 * 32 + lane];
        float e0 = expw(a0 + aldv), e1 = expw(a1 + aldv);
        den += e0 + e1;
        acc.x += e0 * v0.x + e1 * v1.x;
        acc.y += e0 * v0.y + e1 * v1.y;
    }
    if (j < j1) {
        int s0 = csr_src[j];
        float2 v0 = h2[(size_t)s0 * 32 + lane];
        float e0 = expw(als[s0] + aldv);
        den += e0;
        acc.x += e0 * v0.x;
        acc.y += e0 * v0.y;
    }
    float inv = 1.f / den;
    float2 bb = ((const float2*)bias)[lane];
    ((float2*)(out + (size_t)d * 64))[lane] = make_float2(acc.x * inv + bb.x, acc.y * inv + bb.y);
}

__global__ void zero_stats_kernel(float* __restrict__ s, float* __restrict__ s2) {
    s[threadIdx.x] = 0.f;
    s2[threadIdx.x] = 0.f;
}

// ---------------- BN + leakyReLU (+res) fused with bf16 split ----------------
__global__ void bn_split_kernel(const float4* __restrict__ x, const float4* __restrict__ res_in,
                                const float4* __restrict__ gamma4, const float4* __restrict__ beta4,
                                const float4* __restrict__ sums4, const float4* __restrict__ sumsq4,
                                float invn, int n4, float4* __restrict__ res_out,
                                __nv_bfloat162* __restrict__ hi, __nv_bfloat162* __restrict__ lo) {
    int i = blockIdx.x * blockDim.x + threadIdx.x;
    if (i >= n4) return;
    int f4 = i & 63;
    float4 xv = x[i], g = gamma4[f4], b = beta4[f4], s = sums4[f4], q = sumsq4[f4];
    float4 v;
    {
        float mu = s.x * invn, var = q.x * invn - mu * mu;
        v.x = g.x * (xv.x - mu) * rsqrtf(var + 1e-5f) + b.x;
        mu = s.y * invn; var = q.y * invn - mu * mu;
        v.y = g.y * (xv.y - mu) * rsqrtf(var + 1e-5f) + b.y;
        mu = s.z * invn; var = q.z * invn - mu * mu;
        v.z = g.z * (xv.z - mu) * rsqrtf(var + 1e-5f) + b.z;
        mu = s.w * invn; var = q.w * invn - mu * mu;
        v.w = g.w * (xv.w - mu) * rsqrtf(var + 1e-5f) + b.w;
    }
    v.x = v.x > 0.f ? v.x : 0.01f * v.x;
    v.y = v.y > 0.f ? v.y : 0.01f * v.y;
    v.z = v.z > 0.f ? v.z : 0.01f * v.z;
    v.w = v.w > 0.f ? v.w : 0.01f * v.w;
    if (res_in) {
        float4 r = res_in[i];
        v.x += r.x; v.y += r.y; v.z += r.z; v.w += r.w;
    }
    if (res_out) res_out[i] = v;
    __nv_bfloat16 h0 = __float2bfloat16(v.x), h1 = __float2bfloat16(v.y);
    __nv_bfloat16 h2 = __float2bfloat16(v.z), h3 = __float2bfloat16(v.w);
    hi[i * 2 + 0] = __nv_bfloat162(h0, h1);
    hi[i * 2 + 1] = __nv_bfloat162(h2, h3);
    lo[i * 2 + 0] = __nv_bfloat162(__float2bfloat16(v.x - __bfloat162float(h0)),
                                   __float2bfloat16(v.y - __bfloat162float(h1)));
    lo[i * 2 + 1] = __nv_bfloat162(__float2bfloat16(v.z - __bfloat162float(h2)),
                                   __float2bfloat16(v.w - __bfloat162float(h3)));
}

// ---------------- host ----------------
static void run_split(const float* in, __nv_bfloat16* hi, __nv_bfloat16* lo, int n) {
    int n4 = n / 4;
    split_bf16_kernel<<<(n4 + 255) / 256, 256>>>((const float4*)in,
                                                 (__nv_bfloat162*)hi, (__nv_bfloat162*)lo, n4);
}

extern "C" void kernel_launch(void* const* d_in, const int* in_sizes, int n_in,
                              void* d_out, int out_size) {
    const float* x     = (const float*)d_in[0];
    const int*   ei    = (const int*)d_in[1];
    const float* W1    = (const float*)d_in[2];
    const float* a1s   = (const float*)d_in[3];
    const float* a1d   = (const float*)d_in[4];
    const float* b1    = (const float*)d_in[5];
    const float* W2    = (const float*)d_in[6];
    const float* a2s   = (const float*)d_in[7];
    const float* a2d   = (const float*)d_in[8];
    const float* b2    = (const float*)d_in[9];
    const float* W3    = (const float*)d_in[10];
    const float* a3s   = (const float*)d_in[11];
    const float* a3d   = (const float*)d_in[12];
    const float* b3    = (const float*)d_in[13];
    const float* gamma = (const float*)d_in[14];
    const float* beta  = (const float*)d_in[15];
    float* out = (float*)d_out;

    int N = in_sizes[0] / (2 * HD);
    int E = in_sizes[1] / 2;
    int EE = E + N;

    float *h, *acc, *res, *als, *ald, *sums, *sumsq;
    __nv_bfloat16 *ah, *al, *wh, *wl;
    int *counts, *start, *woff, *bsums, *csr_src;
    cudaGetSymbolAddress((void**)&h,       g_h);
    cudaGetSymbolAddress((void**)&acc,     g_acc);
    cudaGetSymbolAddress((void**)&res,     g_res);
    cudaGetSymbolAddress((void**)&ah,      g_ah);
    cudaGetSymbolAddress((void**)&al,      g_al);
    cudaGetSymbolAddress((void**)&wh,      g_wh);
    cudaGetSymbolAddress((void**)&wl,      g_wl);
    cudaGetSymbolAddress((void**)&als,     g_als);
    cudaGetSymbolAddress((void**)&ald,     g_ald);
    cudaGetSymbolAddress((void**)&sums,    g_sums);
    cudaGetSymbolAddress((void**)&sumsq,   g_sumsq);
    cudaGetSymbolAddress((void**)&counts,  g_counts);
    cudaGetSymbolAddress((void**)&start,   g_start);
    cudaGetSymbolAddress((void**)&woff,    g_woff);
    cudaGetSymbolAddress((void**)&bsums,   g_bsums);
    cudaGetSymbolAddress((void**)&csr_src, g_csr_src);

    cudaFuncSetAttribute(gemm_mma3<128>, cudaFuncAttributeMaxDynamicSharedMemorySize, 81920);
    cudaFuncSetAttribute(gemm_mma3<64>,  cudaFuncAttributeMaxDynamicSharedMemorySize, 61440);

    int blocks128 = (N + 127) / 128;
    int nb = (N + 255) / 256;

    // ---- CSR build (reused by all 3 layers) ----
    zero_int_kernel<<<nb, 256>>>(counts, N);
    count_kernel<<<(EE + 255) / 256, 256>>>(ei, E, N, counts);
    scan_block_kernel<<<nb, 256>>>(counts, start, bsums, N);
    scan_sums_kernel<<<1, 256>>>(bsums, nb);
    add_offsets_kernel<<<nb, 256>>>(start, bsums, woff, N, EE);
    fill_kernel<<<(EE + 255) / 256, 256>>>(ei, E, N, woff, csr_src);

    int lw_grid4 = (N * 4 * 32 + 255) / 256;
    int lw_grid1 = (N * 32 + 255) / 256;
    int agg4_grid = (N + 3) / 4;
    int agg1_grid = (N + 7) / 8;
    int n4 = N * 64;

    // ================= layer 1: K=128, H=4 =================
    run_split(x, ah, al, N * 128);
    run_split(W1, wh, wl, 256 * 128);
    gemm_mma3<128><<<dim3(blocks128, 2), 256, 81920>>>(ah, al, wh, wl, h, N, 128, 256);
    logits_warp_kernel<<<lw_grid4, 256>>>(h, a1s, a1d, als, ald, N * 4, 4);
    zero_stats_kernel<<<1, 256>>>(sums, sumsq);
    agg4_kernel<<<agg4_grid, 256>>>(start, csr_src, als, ald, h, b1, acc, N, sums, sumsq, 1);
    bn_split_kernel<<<(n4 + 255) / 256, 256>>>((const float4*)acc, nullptr,
        (const float4*)gamma, (const float4*)beta, (const float4*)sums, (const float4*)sumsq,
        1.0f / (float)N, n4, (float4*)res, (__nv_bfloat162*)ah, (__nv_bfloat162*)al);

    // ================= layer 2: K=256, H=4 =================
    run_split(W2, wh, wl, 256 * 256);
    gemm_mma3<128><<<dim3(blocks128, 2), 256, 81920>>>(ah, al, wh, wl, h, N, 256, 256);
    logits_warp_kernel<<<lw_grid4, 256>>>(h, a2s, a2d, als, ald, N * 4, 4);
    zero_stats_kernel<<<1, 256>>>(sums, sumsq);
    agg4_kernel<<<agg4_grid, 256>>>(start, csr_src, als, ald, h, b2, acc, N, sums, sumsq, 1);
    bn_split_kernel<<<(n4 + 255) / 256, 256>>>((const float4*)acc, (const float4*)res,
        (const float4*)gamma, (const float4*)beta, (const float4*)sums, (const float4*)sumsq,
        1.0f / (float)N, n4, nullptr, (__nv_bfloat162*)ah, (__nv_bfloat162*)al);

    // ================= layer 3: K=256, H=1 =================
    run_split(W3, wh, wl, 64 * 256);
    gemm_mma3<64><<<dim3(blocks128, 1), 256, 61440>>>(ah, al, wh, wl, h, N, 256, 64);
    logits_warp_kernel<<<lw_grid1, 256>>>(h, a3s, a3d, als, ald, N, 1);
    agg1_kernel<<<agg1_grid, 256>>>(start, csr_src, als, ald, h, b3, out, N);
}

// round 8
// speedup vs baseline: 2.0085x; 1.1273x over previous
#include <cuda_runtime.h>
#include <cuda_bf16.h>
#include <cstdint>

// ---------------- problem constants ----------------
#define HD   64
#define NHEADS 4
#define NMAX 50000
#define EMAX 400000
#define EEMAX (EMAX + NMAX)
#define FMAX 256

// ---------------- device scratch ----------------
__device__ float g_h[(size_t)NMAX * FMAX];     // gemm output
__device__ float g_acc[(size_t)NMAX * FMAX];   // aggregation output
__device__ float g_res[(size_t)NMAX * FMAX];   // residual
__device__ __nv_bfloat16 g_ah[(size_t)NMAX * FMAX];
__device__ __nv_bfloat16 g_al[(size_t)NMAX * FMAX];
__device__ __nv_bfloat16 g_w1h[FMAX * FMAX];
__device__ __nv_bfloat16 g_w1l[FMAX * FMAX];
__device__ __nv_bfloat16 g_w2h[FMAX * FMAX];
__device__ __nv_bfloat16 g_w2l[FMAX * FMAX];
__device__ __nv_bfloat16 g_w3h[HD * FMAX];
__device__ __nv_bfloat16 g_w3l[HD * FMAX];
__device__ float g_als[NMAX * NHEADS];
__device__ float g_ald[NMAX * NHEADS];
__device__ float g_sumsA[FMAX];
__device__ float g_sumsqA[FMAX];
__device__ float g_sumsB[FMAX];
__device__ float g_sumsqB[FMAX];
// CSR
__device__ int g_counts[NMAX + 1];
__device__ int g_start[NMAX + 1];
__device__ int g_woff[NMAX];
__device__ int g_bsums[256];
__device__ int g_csr_src[EEMAX];

// ---------------- PTX helpers ----------------
__device__ __forceinline__ uint32_t smem_u32(const void* p) {
    uint32_t a;
    asm("{ .reg .u64 t; cvta.to.shared.u64 t, %1; cvt.u32.u64 %0, t; }" : "=r"(a) : "l"(p));
    return a;
}
__device__ __forceinline__ void cp16z(uint32_t dst, const void* src, uint32_t nbytes) {
    asm volatile("cp.async.cg.shared.global [%0], [%1], 16, %2;"
                 :: "r"(dst), "l"(src), "r"(nbytes));
}
#define CP_COMMIT() asm volatile("cp.async.commit_group;" ::: "memory")
#define LDMATRIX_X4(R0, R1, R2, R3, ADDR)                                   \
    asm volatile("ldmatrix.sync.aligned.m8n8.x4.shared.b16 {%0,%1,%2,%3}, [%4];" \
                 : "=r"(R0), "=r"(R1), "=r"(R2), "=r"(R3) : "r"(ADDR))
#define MMA_BF16(C, A, B)                                                   \
    asm volatile("mma.sync.aligned.m16n8k16.row.col.f32.bf16.bf16.f32 "     \
                 "{%0,%1,%2,%3}, {%4,%5,%6,%7}, {%8,%9}, {%0,%1,%2,%3};"    \
                 : "+f"((C)[0]), "+f"((C)[1]), "+f"((C)[2]), "+f"((C)[3])   \
                 : "r"((A)[0]), "r"((A)[1]), "r"((A)[2]), "r"((A)[3]),      \
                   "r"((B)[0]), "r"((B)[1]))

__device__ __forceinline__ float expw(float v) {
    v = v > 0.f ? v : 0.2f * v;
    return __expf(v);
}

// ---------------- fp32 -> bf16 hi/lo split ----------------
__global__ void split_bf16_kernel(const float4* __restrict__ in,
                                  __nv_bfloat162* __restrict__ hi,
                                  __nv_bfloat162* __restrict__ lo, int n4) {
    int i = blockIdx.x * blockDim.x + threadIdx.x;
    if (i >= n4) return;
    float4 v = in[i];
    __nv_bfloat16 h0 = __float2bfloat16(v.x), h1 = __float2bfloat16(v.y);
    __nv_bfloat16 h2 = __float2bfloat16(v.z), h3 = __float2bfloat16(v.w);
    hi[i * 2 + 0] = __nv_bfloat162(h0, h1);
    hi[i * 2 + 1] = __nv_bfloat162(h2, h3);
    lo[i * 2 + 0] = __nv_bfloat162(__float2bfloat16(v.x - __bfloat162float(h0)),
                                   __float2bfloat16(v.y - __bfloat162float(h1)));
    lo[i * 2 + 1] = __nv_bfloat162(__float2bfloat16(v.z - __bfloat162float(h2)),
                                   __float2bfloat16(v.w - __bfloat162float(h3)));
}

// ---------------- HMMA GEMM + fused logits epilogue ----------------
// C = Ah*Wh^T + Ah*Wl^T + Al*Wh^T; als/ald computed from acc fragments.
// CTA tile 128 x NTILE, 256 threads. Hh = NTILE==128 ? 4 : 1.
template<int NTILE>
__global__ void __launch_bounds__(256) gemm_mma3(
    const __nv_bfloat16* __restrict__ Ah, const __nv_bfloat16* __restrict__ Al,
    const __nv_bfloat16* __restrict__ Wh, const __nv_bfloat16* __restrict__ Wl,
    float* __restrict__ C, int Nrows, int K, int NOUT,
    const float* __restrict__ a_s, const float* __restrict__ a_d,
    float* __restrict__ als, float* __restrict__ ald) {
    constexpr int RS = 40;
    constexpr int MT = (NTILE == 128) ? 2 : 1;
    constexpr int WN = NTILE / 64;
    constexpr int HH = (NTILE == 128) ? 4 : 1;
    constexpr int A_BYTES = 128 * RS * 2;
    constexpr int W_BYTES = NTILE * RS * 2;
    constexpr int STAGE = 2 * A_BYTES + 2 * W_BYTES;
    extern __shared__ char dsm[];
    const uint32_t sbase = smem_u32(dsm);
    const int tid = threadIdx.x, lane = tid & 31, wid = tid >> 5;
    const int wm = wid / WN, wn = wid % WN;
    const int row0 = blockIdx.x * 128, col0 = blockIdx.y * NTILE;

    const int a_row  = ((lane >> 3) & 1) * 8 + (lane & 7);
    const int a_koff = ((lane >> 4) & 1) * 8;
    const int b_row  = ((lane >> 4) & 1) * 8 + (lane & 7);
    const int b_koff = ((lane >> 3) & 1) * 8;
    const uint32_t a_off = (uint32_t)(((wm * 16 * MT + a_row) * RS + a_koff) * 2);
    const uint32_t b_off = (uint32_t)(((wn * 64 + b_row) * RS + b_koff) * 2);

    float acc[MT][8][4];
    #pragma unroll
    for (int mt = 0; mt < MT; mt++)
        #pragma unroll
        for (int nt = 0; nt < 8; nt++)
            #pragma unroll
            for (int j = 0; j < 4; j++) acc[mt][nt][j] = 0.f;

    const int nchunks = K >> 5;

    auto issue_chunk = [&](int ck) {
        const int st = ck & 1;
        const uint32_t ah_s = sbase + st * STAGE;
        const uint32_t al_s = ah_s + A_BYTES;
        const uint32_t wh_s = al_s + A_BYTES;
        const uint32_t wl_s = wh_s + W_BYTES;
        const int k0 = ck << 5;
        #pragma unroll 2
        for (int i = tid; i < 512; i += 256) {
            int r = i >> 2, c16 = i & 3;
            int gr = row0 + r;
            uint32_t nb = (gr < Nrows) ? 16u : 0u;
            if (gr >= Nrows) gr = Nrows - 1;
            const char* pa = (const char*)(Ah + (size_t)gr * K + k0) + c16 * 16;
            const char* pl = (const char*)(Al + (size_t)gr * K + k0) + c16 * 16;
            uint32_t dof = (uint32_t)(r * RS + c16 * 8) * 2;
            cp16z(ah_s + dof, pa, nb);
            cp16z(al_s + dof, pl, nb);
        }
        #pragma unroll 2
        for (int i = tid; i < NTILE * 4; i += 256) {
            int r = i >> 2, c16 = i & 3;
            const char* pw = (const char*)(Wh + (size_t)(col0 + r) * K + k0) + c16 * 16;
            const char* pv = (const char*)(Wl + (size_t)(col0 + r) * K + k0) + c16 * 16;
            uint32_t dof = (uint32_t)(r * RS + c16 * 8) * 2;
            cp16z(wh_s + dof, pw, 16u);
            cp16z(wl_s + dof, pv, 16u);
        }
        CP_COMMIT();
    };

    issue_chunk(0);
    for (int ck = 0; ck < nchunks; ck++) {
        if (ck + 1 < nchunks) {
            issue_chunk(ck + 1);
            asm volatile("cp.async.wait_group 1;" ::: "memory");
        } else {
            asm volatile("cp.async.wait_group 0;" ::: "memory");
        }
        __syncthreads();
        const int st = ck & 1;
        const uint32_t ahb = sbase + st * STAGE;
        const uint32_t alb = ahb + A_BYTES;
        const uint32_t whb = alb + A_BYTES;
        const uint32_t wlb = whb + W_BYTES;
        #pragma unroll
        for (int kk = 0; kk < 32; kk += 16) {
            uint32_t ah_f[MT][4], al_f[MT][4];
            #pragma unroll
            for (int mt = 0; mt < MT; mt++) {
                uint32_t o = a_off + (uint32_t)((mt * 16 * RS + kk) * 2);
                LDMATRIX_X4(ah_f[mt][0], ah_f[mt][1], ah_f[mt][2], ah_f[mt][3], ahb + o);
                LDMATRIX_X4(al_f[mt][0], al_f[mt][1], al_f[mt][2], al_f[mt][3], alb + o);
            }
            uint32_t bh_f[8][2], bl_f[8][2];
            #pragma unroll
            for (int nt16 = 0; nt16 < 4; nt16++) {
                uint32_t o = b_off + (uint32_t)((nt16 * 16 * RS + kk) * 2);
                uint32_t r0, r1, r2, r3;
                LDMATRIX_X4(r0, r1, r2, r3, whb + o);
                bh_f[nt16 * 2 + 0][0] = r0; bh_f[nt16 * 2 + 0][1] = r1;
                bh_f[nt16 * 2 + 1][0] = r2; bh_f[nt16 * 2 + 1][1] = r3;
                LDMATRIX_X4(r0, r1, r2, r3, wlb + o);
                bl_f[nt16 * 2 + 0][0] = r0; bl_f[nt16 * 2 + 0][1] = r1;
                bl_f[nt16 * 2 + 1][0] = r2; bl_f[nt16 * 2 + 1][1] = r3;
            }
            #pragma unroll
            for (int mt = 0; mt < MT; mt++)
                #pragma unroll
                for (int nt = 0; nt < 8; nt++) {
                    MMA_BF16(acc[mt][nt], ah_f[mt], bh_f[nt]);
                    MMA_BF16(acc[mt][nt], ah_f[mt], bl_f[nt]);
                    MMA_BF16(acc[mt][nt], al_f[mt], bh_f[nt]);
                }
        }
        __syncthreads();
    }

    // ---- store C ----
    #pragma unroll
    for (int mt = 0; mt < MT; mt++) {
        int mrow = row0 + wm * 16 * MT + mt * 16 + (lane >> 2);
        #pragma unroll
        for (int nt = 0; nt < 8; nt++) {
            int ncol = col0 + wn * 64 + nt * 8 + (lane & 3) * 2;
            if (mrow < Nrows)
                *(float2*)&C[(size_t)mrow * NOUT + ncol] = make_float2(acc[mt][nt][0], acc[mt][nt][1]);
            if (mrow + 8 < Nrows)
                *(float2*)&C[(size_t)(mrow + 8) * NOUT + ncol] = make_float2(acc[mt][nt][2], acc[mt][nt][3]);
        }
    }

    // ---- fused logits: this warp owns head hd's 64-col segment for its rows ----
    const int hd = blockIdx.y * WN + wn;
    const float* avs = a_s + hd * HD;
    const float* avd = a_d + hd * HD;
    float as_v[16], ad_v[16];
    #pragma unroll
    for (int nt = 0; nt < 8; nt++) {
        int c = nt * 8 + (lane & 3) * 2;
        as_v[nt * 2 + 0] = avs[c];     as_v[nt * 2 + 1] = avs[c + 1];
        ad_v[nt * 2 + 0] = avd[c];     ad_v[nt * 2 + 1] = avd[c + 1];
    }
    #pragma unroll
    for (int mt = 0; mt < MT; mt++) {
        #pragma unroll
        for (int rr = 0; rr < 2; rr++) {
            float ds = 0.f, dd = 0.f;
            #pragma unroll
            for (int nt = 0; nt < 8; nt++) {
                float v0 = acc[mt][nt][rr * 2 + 0], v1 = acc[mt][nt][rr * 2 + 1];
                ds += v0 * as_v[nt * 2] + v1 * as_v[nt * 2 + 1];
                dd += v0 * ad_v[nt * 2] + v1 * ad_v[nt * 2 + 1];
            }
            ds += __shfl_xor_sync(0xffffffff, ds, 1);
            ds += __shfl_xor_sync(0xffffffff, ds, 2);
            dd += __shfl_xor_sync(0xffffffff, dd, 1);
            dd += __shfl_xor_sync(0xffffffff, dd, 2);
            int row = row0 + wm * 16 * MT + mt * 16 + rr * 8 + (lane >> 2);
            if ((lane & 3) == 0 && row < Nrows) {
                als[row * HH + hd] = ds;
                ald[row * HH + hd] = dd;
            }
        }
    }
}

// ---------------- CSR build ----------------
__global__ void zero_int_kernel(int* __restrict__ p, int n) {
    int i = blockIdx.x * blockDim.x + threadIdx.x;
    if (i < n) p[i] = 0;
}
__global__ void count_kernel(const int* __restrict__ ei, int E, int N, int* __restrict__ cnt) {
    int e = blockIdx.x * blockDim.x + threadIdx.x;
    int EE = E + N;
    if (e >= EE) return;
    int d = (e < E) ? ei[E + e] : e - E;
    atomicAdd(&cnt[d], 1);
}
__global__ void scan_block_kernel(const int* __restrict__ cnt, int* __restrict__ excl,
                                  int* __restrict__ bsums, int N) {
    __shared__ int sh[256];
    int tid = threadIdx.x;
    int i = blockIdx.x * 256 + tid;
    int v = (i < N) ? cnt[i] : 0;
    sh[tid] = v;
    __syncthreads();
    #pragma unroll
    for (int off = 1; off < 256; off <<= 1) {
        int t = (tid >= off) ? sh[tid - off] : 0;
        __syncthreads();
        sh[tid] += t;
        __syncthreads();
    }
    if (i < N) excl[i] = sh[tid] - v;
    if (tid == 255) bsums[blockIdx.x] = sh[255];
}
__global__ void scan_sums_kernel(int* __restrict__ bsums, int nb) {
    __shared__ int sh[256];
    int tid = threadIdx.x;
    int v = (tid < nb) ? bsums[tid] : 0;
    sh[tid] = v;
    __syncthreads();
    #pragma unroll
    for (int off = 1; off < 256; off <<= 1) {
        int t = (tid >= off) ? sh[tid - off] : 0;
        __syncthreads();
        sh[tid] += t;
        __syncthreads();
    }
    if (tid < nb) bsums[tid] = sh[tid] - v;
}
__global__ void add_offsets_kernel(int* __restrict__ excl, const int* __restrict__ bsums,
                                   int* __restrict__ woff, int N, int EE) {
    int i = blockIdx.x * 256 + threadIdx.x;
    if (i < N) {
        int v = excl[i] + bsums[blockIdx.x];
        excl[i] = v;
        woff[i] = v;
    }
    if (blockIdx.x == 0 && threadIdx.x == 0) excl[N] = EE;
}
__global__ void fill_kernel(const int* __restrict__ ei, int E, int N,
                            int* __restrict__ woff, int* __restrict__ csr_src) {
    int e = blockIdx.x * blockDim.x + threadIdx.x;
    int EE = E + N;
    if (e >= EE) return;
    int s, d;
    if (e < E) { s = ei[e]; d = ei[E + e]; }
    else       { s = d = e - E; }
    int pos = atomicAdd(&woff[d], 1);
    csr_src[pos] = s;
}

// ---------------- CSR aggregation, H=4: 2 warps per dst (feature halves) ----------------
__global__ void __launch_bounds__(256) agg4_kernel(
    const int* __restrict__ start, const int* __restrict__ csr_src,
    const float* __restrict__ als, const float* __restrict__ ald,
    const float* __restrict__ h, const float* __restrict__ bias,
    float* __restrict__ out, int N,
    float* __restrict__ sums, float* __restrict__ sumsq) {
    __shared__ float s_s[256], s_q[256];
    int tid = threadIdx.x, lane = tid & 31, wid = tid >> 5;
    s_s[tid] = 0.f; s_q[tid] = 0.f;
    __syncthreads();
    int d = blockIdx.x * 4 + (wid >> 1);
    int half = wid & 1;
    if (d < N) {
        const float2* als2 = (const float2*)als;
        float2 aldv = ((const float2*)ald)[d * 2 + half];
        float den0 = 0.f, den1 = 0.f;
        float4 acc = make_float4(0.f, 0.f, 0.f, 0.f);
        const float4* h4 = (const float4*)h;
        int c4 = half * 32 + lane;
        int j0 = start[d], j1 = start[d + 1];
        int j = j0;
        for (; j + 2 <= j1; j += 2) {
            int s0 = csr_src[j], s1 = csr_src[j + 1];
            float2 a0 = als2[s0 * 2 + half];
            float2 a1 = als2[s1 * 2 + half];
            float4 v0 = h4[(size_t)s0 * 64 + c4];
            float4 v1 = h4[(size_t)s1 * 64 + c4];
            float e00 = expw(a0.x + aldv.x), e01 = expw(a0.y + aldv.y);
            float e10 = expw(a1.x + aldv.x), e11 = expw(a1.y + aldv.y);
            den0 += e00 + e10;
            den1 += e01 + e11;
            float w0 = (lane < 16) ? e00 : e01;
            float w1 = (lane < 16) ? e10 : e11;
            acc.x += w0 * v0.x + w1 * v1.x;
            acc.y += w0 * v0.y + w1 * v1.y;
            acc.z += w0 * v0.z + w1 * v1.z;
            acc.w += w0 * v0.w + w1 * v1.w;
        }
        if (j < j1) {
            int s0 = csr_src[j];
            float2 a0 = als2[s0 * 2 + half];
            float4 v0 = h4[(size_t)s0 * 64 + c4];
            float e00 = expw(a0.x + aldv.x), e01 = expw(a0.y + aldv.y);
            den0 += e00;
            den1 += e01;
            float w0 = (lane < 16) ? e00 : e01;
            acc.x += w0 * v0.x; acc.y += w0 * v0.y;
            acc.z += w0 * v0.z; acc.w += w0 * v0.w;
        }
        float inv = 1.f / ((lane < 16) ? den0 : den1);
        float4 bb = ((const float4*)bias)[c4];
        float4 r = make_float4(acc.x * inv + bb.x, acc.y * inv + bb.y,
                               acc.z * inv + bb.z, acc.w * inv + bb.w);
        ((float4*)(out + (size_t)d * 256))[c4] = r;
        int f = c4 * 4;
        atomicAdd(&s_s[f + 0], r.x); atomicAdd(&s_q[f + 0], r.x * r.x);
        atomicAdd(&s_s[f + 1], r.y); atomicAdd(&s_q[f + 1], r.y * r.y);
        atomicAdd(&s_s[f + 2], r.z); atomicAdd(&s_q[f + 2], r.z * r.z);
        atomicAdd(&s_s[f + 3], r.w); atomicAdd(&s_q[f + 3], r.w * r.w);
    }
    __syncthreads();
    atomicAdd(&sums[tid], s_s[tid]);
    atomicAdd(&sumsq[tid], s_q[tid]);
}

// ---------------- CSR aggregation, H=1 (F=64) ----------------
__global__ void __launch_bounds__(256) agg1_kernel(
    const int* __restrict__ start, const int* __restrict__ csr_src,
    const float* __restrict__ als, const float* __restrict__ ald,
    const float* __restrict__ h, const float* __restrict__ bias,
    float* __restrict__ out, int N) {
    int tid = threadIdx.x, lane = tid & 31, wid = tid >> 5;
    int d = blockIdx.x * 8 + wid;
    if (d >= N) return;
    float aldv = ald[d];
    float den = 0.f;
    float2 acc = make_float2(0.f, 0.f);
    const float2* h2 = (const float2*)h;
    int j0 = start[d], j1 = start[d + 1];
    int j = j0;
    for (; j + 2 <= j1; j += 2) {
        int s0 = csr_src[j], s1 = csr_src[j + 1];
        float a0 = als[s0], a1 = als[s1];
        float2 v0 = h2[(size_t)s0 * 32 + lane];
        float2 v1 = h2[(size_t)s1 * 32 + lane];
        float e0 = expw(a0 + aldv), e1 = expw(a1 + aldv);
        den += e0 + e1;
        acc.x += e0 * v0.x + e1 * v1.x;
        acc.y += e0 * v0.y + e1 * v1.y;
    }
    if (j < j1) {
        int s0 = csr_src[j];
        float2 v0 = h2[(size_t)s0 * 32 + lane];
        float e0 = expw(als[s0] + aldv);
        den += e0;
        acc.x += e0 * v0.x;
        acc.y += e0 * v0.y;
    }
    float inv = 1.f / den;
    float2 bb = ((const float2*)bias)[lane];
    ((float2*)(out + (size_t)d * 64))[lane] = make_float2(acc.x * inv + bb.x, acc.y * inv + bb.y);
}

__global__ void zero_stats2_kernel(float* __restrict__ sA, float* __restrict__ qA,
                                   float* __restrict__ sB, float* __restrict__ qB) {
    sA[threadIdx.x] = 0.f; qA[threadIdx.x] = 0.f;
    sB[threadIdx.x] = 0.f; qB[threadIdx.x] = 0.f;
}

// ---------------- BN + leakyReLU (+res) fused with bf16 split ----------------
__global__ void bn_split_kernel(const float4* __restrict__ x, const float4* __restrict__ res_in,
                                const float4* __restrict__ gamma4, const float4* __restrict__ beta4,
                                const float4* __restrict__ sums4, const float4* __restrict__ sumsq4,
                                float invn, int n4, float4* __restrict__ res_out,
                                __nv_bfloat162* __restrict__ hi, __nv_bfloat162* __restrict__ lo) {
    int i = blockIdx.x * blockDim.x + threadIdx.x;
    if (i >= n4) return;
    int f4 = i & 63;
    float4 xv = x[i], g = gamma4[f4], b = beta4[f4], s = sums4[f4], q = sumsq4[f4];
    float4 v;
    {
        float mu = s.x * invn, var = q.x * invn - mu * mu;
        v.x = g.x * (xv.x - mu) * rsqrtf(var + 1e-5f) + b.x;
        mu = s.y * invn; var = q.y * invn - mu * mu;
        v.y = g.y * (xv.y - mu) * rsqrtf(var + 1e-5f) + b.y;
        mu = s.z * invn; var = q.z * invn - mu * mu;
        v.z = g.z * (xv.z - mu) * rsqrtf(var + 1e-5f) + b.z;
        mu = s.w * invn; var = q.w * invn - mu * mu;
        v.w = g.w * (xv.w - mu) * rsqrtf(var + 1e-5f) + b.w;
    }
    v.x = v.x > 0.f ? v.x : 0.01f * v.x;
    v.y = v.y > 0.f ? v.y : 0.01f * v.y;
    v.z = v.z > 0.f ? v.z : 0.01f * v.z;
    v.w = v.w > 0.f ? v.w : 0.01f * v.w;
    if (res_in) {
        float4 r = res_in[i];
        v.x += r.x; v.y += r.y; v.z += r.z; v.w += r.w;
    }
    if (res_out) res_out[i] = v;
    __nv_bfloat16 h0 = __float2bfloat16(v.x), h1 = __float2bfloat16(v.y);
    __nv_bfloat16 h2 = __float2bfloat16(v.z), h3 = __float2bfloat16(v.w);
    hi[i * 2 + 0] = __nv_bfloat162(h0, h1);
    hi[i * 2 + 1] = __nv_bfloat162(h2, h3);
    lo[i * 2 + 0] = __nv_bfloat162(__float2bfloat16(v.x - __bfloat162float(h0)),
                                   __float2bfloat16(v.y - __bfloat162float(h1)));
    lo[i * 2 + 1] = __nv_bfloat162(__float2bfloat16(v.z - __bfloat162float(h2)),
                                   __float2bfloat16(v.w - __bfloat162float(h3)));
}

// ---------------- host ----------------
static void split_on(cudaStream_t st, const float* in, __nv_bfloat16* hi, __nv_bfloat16* lo, int n) {
    int n4 = n / 4;
    split_bf16_kernel<<<(n4 + 255) / 256, 256, 0, st>>>((const float4*)in,
                                                        (__nv_bfloat162*)hi, (__nv_bfloat162*)lo, n4);
}

extern "C" void kernel_launch(void* const* d_in, const int* in_sizes, int n_in,
                              void* d_out, int out_size) {
    const float* x     = (const float*)d_in[0];
    const int*   ei    = (const int*)d_in[1];
    const float* W1    = (const float*)d_in[2];
    const float* a1s   = (const float*)d_in[3];
    const float* a1d   = (const float*)d_in[4];
    const float* b1    = (const float*)d_in[5];
    const float* W2    = (const float*)d_in[6];
    const float* a2s   = (const float*)d_in[7];
    const float* a2d   = (const float*)d_in[8];
    const float* b2    = (const float*)d_in[9];
    const float* W3    = (const float*)d_in[10];
    const float* a3s   = (const float*)d_in[11];
    const float* a3d   = (const float*)d_in[12];
    const float* b3    = (const float*)d_in[13];
    const float* gamma = (const float*)d_in[14];
    const float* beta  = (const float*)d_in[15];
    float* out = (float*)d_out;

    int N = in_sizes[0] / (2 * HD);
    int E = in_sizes[1] / 2;
    int EE = E + N;

    float *h, *acc, *res, *als, *ald, *sumsA, *sumsqA, *sumsB, *sumsqB;
    __nv_bfloat16 *ah, *al, *w1h, *w1l, *w2h, *w2l, *w3h, *w3l;
    int *counts, *start, *woff, *bsums, *csr_src;
    cudaGetSymbolAddress((void**)&h,       g_h);
    cudaGetSymbolAddress((void**)&acc,     g_acc);
    cudaGetSymbolAddress((void**)&res,     g_res);
    cudaGetSymbolAddress((void**)&ah,      g_ah);
    cudaGetSymbolAddress((void**)&al,      g_al);
    cudaGetSymbolAddress((void**)&w1h,     g_w1h);
    cudaGetSymbolAddress((void**)&w1l,     g_w1l);
    cudaGetSymbolAddress((void**)&w2h,     g_w2h);
    cudaGetSymbolAddress((void**)&w2l,     g_w2l);
    cudaGetSymbolAddress((void**)&w3h,     g_w3h);
    cudaGetSymbolAddress((void**)&w3l,     g_w3l);
    cudaGetSymbolAddress((void**)&als,     g_als);
    cudaGetSymbolAddress((void**)&ald,     g_ald);
    cudaGetSymbolAddress((void**)&sumsA,   g_sumsA);
    cudaGetSymbolAddress((void**)&sumsqA,  g_sumsqA);
    cudaGetSymbolAddress((void**)&sumsB,   g_sumsB);
    cudaGetSymbolAddress((void**)&sumsqB,  g_sumsqB);
    cudaGetSymbolAddress((void**)&counts,  g_counts);
    cudaGetSymbolAddress((void**)&start,   g_start);
    cudaGetSymbolAddress((void**)&woff,    g_woff);
    cudaGetSymbolAddress((void**)&bsums,   g_bsums);
    cudaGetSymbolAddress((void**)&csr_src, g_csr_src);

    cudaFuncSetAttribute(gemm_mma3<128>, cudaFuncAttributeMaxDynamicSharedMemorySize, 81920);
    cudaFuncSetAttribute(gemm_mma3<64>,  cudaFuncAttributeMaxDynamicSharedMemorySize, 61440);

    static cudaStream_t side = nullptr;
    static cudaEvent_t evFork = nullptr, evSide = nullptr;
    if (!side) {
        cudaStreamCreateWithFlags(&side, cudaStreamNonBlocking);
        cudaEventCreateWithFlags(&evFork, cudaEventDisableTiming);
        cudaEventCreateWithFlags(&evSide, cudaEventDisableTiming);
    }

    int blocks128 = (N + 127) / 128;
    int nb = (N + 255) / 256;
    int agg4_grid = (N + 3) / 4;
    int agg1_grid = (N + 7) / 8;
    int n4 = N * 64;

    // ---- fork side stream: CSR build + W2/W3 splits + stat zero ----
    cudaEventRecord(evFork, 0);
    cudaStreamWaitEvent(side, evFork, 0);
    zero_stats2_kernel<<<1, 256, 0, side>>>(sumsA, sumsqA, sumsB, sumsqB);
    zero_int_kernel<<<nb, 256, 0, side>>>(counts, N);
    count_kernel<<<(EE + 255) / 256, 256, 0, side>>>(ei, E, N, counts);
    scan_block_kernel<<<nb, 256, 0, side>>>(counts, start, bsums, N);
    scan_sums_kernel<<<1, 256, 0, side>>>(bsums, nb);
    add_offsets_kernel<<<nb, 256, 0, side>>>(start, bsums, woff, N, EE);
    fill_kernel<<<(EE + 255) / 256, 256, 0, side>>>(ei, E, N, woff, csr_src);
    split_on(side, W2, w2h, w2l, 256 * 256);
    split_on(side, W3, w3h, w3l, 64 * 256);
    cudaEventRecord(evSide, side);

    // ---- main: layer 1 GEMM chain ----
    split_on(0, W1, w1h, w1l, 256 * 128);
    split_on(0, x, ah, al, N * 128);
    gemm_mma3<128><<<dim3(blocks128, 2), 256, 81920>>>(ah, al, w1h, w1l, h, N, 128, 256,
                                                       a1s, a1d, als, ald);
    cudaStreamWaitEvent(0, evSide, 0);   // join: CSR, stats-zero, W2/W3 ready
    agg4_kernel<<<agg4_grid, 256>>>(start, csr_src, als, ald, h, b1, acc, N, sumsA, sumsqA);
    bn_split_kernel<<<(n4 + 255) / 256, 256>>>((const float4*)acc, nullptr,
        (const float4*)gamma, (const float4*)beta, (const float4*)sumsA, (const float4*)sumsqA,
        1.0f / (float)N, n4, (float4*)res, (__nv_bfloat162*)ah, (__nv_bfloat162*)al);

    // ---- layer 2 ----
    gemm_mma3<128><<<dim3(blocks128, 2), 256, 81920>>>(ah, al, w2h, w2l, h, N, 256, 256,
                                                       a2s, a2d, als, ald);
    agg4_kernel<<<agg4_grid, 256>>>(start, csr_src, als, ald, h, b2, acc, N, sumsB, sumsqB);
    bn_split_kernel<<<(n4 + 255) / 256, 256>>>((const float4*)acc, (const float4*)res,
        (const float4*)gamma, (const float4*)beta, (const float4*)sumsB, (const float4*)sumsqB,
        1.0f / (float)N, n4, nullptr, (__nv_bfloat162*)ah, (__nv_bfloat162*)al);

    // ---- layer 3 ----
    gemm_mma3<64><<<dim3(blocks128, 1), 256, 61440>>>(ah, al, w3h, w3l, h, N, 256, 64,
                                                      a3s, a3d, als, ald);
    agg1_kernel<<<agg1_grid, 256>>>(start, csr_src, als, ald, h, b3, out, N);
}